// round 1
// baseline (speedup 1.0000x reference)
#include <cuda_runtime.h>

#define WIN_N 49
#define DIMC  128
#define NH    4
#define HD    32
#define QSCALE 0.17677669529663687f  /* 32^-0.5 */

// ---- dynamic smem layout (floats) ----
// sx    [49*128]      = 6272   (reused as attention output before proj)
// swb   [16*384]      = 6144   (weight chunk buffer; proj uses 16*128 subset)
// sq    [49*128]      = 6272   (q, pre-scaled)
// skT   [4*32*56]     = 7168   (k transposed: [h][d][j], j-stride 56)
// sv    [49*128]      = 6272
// sattn [4*49*56]     = 10976  ([h][i][j], j-stride 56)
// total = 43104 floats = 172416 bytes
#define OFF_SX    0
#define OFF_SWB   6272
#define OFF_SQ    12416
#define OFF_SKT   18688
#define OFF_SV    25856
#define OFF_SATTN 32128
#define SMEM_FLOATS 43104
#define SMEM_BYTES  (SMEM_FLOATS * 4)

__global__ __launch_bounds__(256, 1)
void win_attn_kernel(const float* __restrict__ x,
                     const float* __restrict__ mask,
                     const float* __restrict__ qkv_w,
                     const float* __restrict__ qkv_b,
                     const float* __restrict__ proj_w,
                     const float* __restrict__ proj_b,
                     const float* __restrict__ bias_table,
                     const int*   __restrict__ rel_index,
                     float* __restrict__ out,
                     int nW)
{
    extern __shared__ float sm[];
    float* sx    = sm + OFF_SX;
    float* swb   = sm + OFF_SWB;
    float* sq    = sm + OFF_SQ;
    float* skT   = sm + OFF_SKT;
    float* sv    = sm + OFF_SV;
    float* sattn = sm + OFF_SATTN;

    const int b   = blockIdx.x;
    const int tid = threadIdx.x;
    const int tx  = tid & 31;   // column lane
    const int ty  = tid >> 5;   // row group / warp id

    // ---------------- load x window [49,128] ----------------
    {
        const float4* gx  = (const float4*)(x + (size_t)b * (WIN_N * DIMC));
        float4*       sx4 = (float4*)sx;
        #pragma unroll
        for (int i = 0; i < 7; ++i) {
            int idx = tid + 256 * i;
            if (idx < (WIN_N * DIMC / 4)) sx4[idx] = gx[idx];
        }
    }

    // ---------------- QKV GEMM: [49,128] @ [128,384] + b ----------------
    // thread tile: rows r = ty + 8*i (i<7), cols c = tx + 32*j (j<12)
    float acc[7][12];
    {
        float bb[12];
        #pragma unroll
        for (int j = 0; j < 12; ++j) bb[j] = qkv_b[tx + 32 * j];
        #pragma unroll
        for (int i = 0; i < 7; ++i)
            #pragma unroll
            for (int j = 0; j < 12; ++j) acc[i][j] = bb[j];
    }

    float4 pre[6];
    {   // preload W chunk 0 (16 rows x 384 cols = 1536 float4)
        const float4* gw = (const float4*)qkv_w;
        #pragma unroll
        for (int q = 0; q < 6; ++q) pre[q] = gw[tid + 256 * q];
    }
    __syncthreads();  // sx ready

    for (int c = 0; c < 8; ++c) {
        {   // store prefetched chunk to smem
            float4* swb4 = (float4*)swb;
            #pragma unroll
            for (int q = 0; q < 6; ++q) swb4[tid + 256 * q] = pre[q];
        }
        __syncthreads();
        if (c < 7) {  // prefetch next chunk (overlaps compute)
            const float4* gw = (const float4*)(qkv_w + (c + 1) * 16 * 384);
            #pragma unroll
            for (int q = 0; q < 6; ++q) pre[q] = gw[tid + 256 * q];
        }
        const int kc = c * 16;
        #pragma unroll 4
        for (int k = 0; k < 16; ++k) {
            float xv[7];
            #pragma unroll
            for (int i = 0; i < 7; ++i) {
                int r = ty + 8 * i; r = (r < WIN_N) ? r : (WIN_N - 1);
                xv[i] = sx[r * DIMC + kc + k];   // warp-broadcast
            }
            float wv[12];
            #pragma unroll
            for (int j = 0; j < 12; ++j) wv[j] = swb[k * 384 + tx + 32 * j];
            #pragma unroll
            for (int i = 0; i < 7; ++i)
                #pragma unroll
                for (int j = 0; j < 12; ++j) acc[i][j] += xv[i] * wv[j];
        }
        __syncthreads();  // chunk consumed before overwrite
    }

    // scatter to sq (scaled) / skT (transposed) / sv
    #pragma unroll
    for (int i = 0; i < 7; ++i) {
        int r = ty + 8 * i;
        if (r < WIN_N) {
            #pragma unroll
            for (int j = 0; j < 12; ++j) {
                int ccol = tx + 32 * j;
                float v = acc[i][j];
                if (ccol < 128) {
                    sq[r * DIMC + ccol] = v * QSCALE;
                } else if (ccol < 256) {
                    int cc = ccol - 128;
                    skT[(cc >> 5) * (HD * 56) + (cc & 31) * 56 + r] = v;
                } else {
                    sv[r * DIMC + (ccol - 256)] = v;
                }
            }
        }
    }
    __syncthreads();

    // ---------------- attention (per-warp rows, 2 warps per head) ----------------
    {
        const int h   = ty >> 1;
        const int sub = ty & 1;
        const int lane = tx;
        const float* masks = mask + (size_t)(b % nW) * (WIN_N * WIN_N);
        const float* kt = skT + h * (HD * 56);
        float* at = sattn + h * (WIN_N * 56);

        for (int i = sub; i < WIN_N; i += 2) {
            const int j0 = lane;
            const int j1 = lane + 32;
            const bool v1 = (j1 < WIN_N);
            const int j1c = v1 ? j1 : 0;

            // bias gather (issued early to hide L2 latency under the dot loop)
            int   idx0 = rel_index[i * WIN_N + j0];
            float add0 = masks[i * WIN_N + j0];
            int   idx1 = rel_index[i * WIN_N + j1c];
            float add1 = masks[i * WIN_N + j1c];

            const float* qr = sq + i * DIMC + h * HD;
            float d0 = 0.f, d1 = 0.f;
            #pragma unroll
            for (int d = 0; d < HD; ++d) {
                float qd = qr[d];                 // broadcast
                d0 += qd * kt[d * 56 + j0];       // stride-1, conflict-free
                d1 += qd * kt[d * 56 + j1c];
            }
            d0 += bias_table[idx0 * NH + h] + add0;
            d1 = v1 ? (d1 + bias_table[idx1 * NH + h] + add1) : -1e30f;

            // softmax over 49 values held as (d0 all lanes, d1 lanes<17)
            float mx = fmaxf(d0, d1);
            #pragma unroll
            for (int o = 16; o > 0; o >>= 1)
                mx = fmaxf(mx, __shfl_xor_sync(0xffffffffu, mx, o));
            float e0 = __expf(d0 - mx);
            float e1 = v1 ? __expf(d1 - mx) : 0.f;
            float s = e0 + e1;
            #pragma unroll
            for (int o = 16; o > 0; o >>= 1)
                s += __shfl_xor_sync(0xffffffffu, s, o);
            float inv = 1.0f / s;

            at[i * 56 + j0] = e0 * inv;
            if (v1) at[i * 56 + j1] = e1 * inv;
            __syncwarp();

            // attn row @ v  ->  sout row (lane = d)
            float a = 0.f;
            const float* ar   = at + i * 56;
            const float* vcol = sv + h * HD + lane;
            #pragma unroll
            for (int j = 0; j < WIN_N; ++j)
                a += ar[j] * vcol[j * DIMC];      // ar broadcast, vcol stride-1
            sx[i * DIMC + h * HD + lane] = a;     // sout reuses sx
        }
    }
    __syncthreads();

    // ---------------- proj GEMM: [49,128] @ [128,128] + b ----------------
    float pacc[7][4];
    {
        float pb[4];
        #pragma unroll
        for (int j = 0; j < 4; ++j) pb[j] = proj_b[tx + 32 * j];
        #pragma unroll
        for (int i = 0; i < 7; ++i)
            #pragma unroll
            for (int j = 0; j < 4; ++j) pacc[i][j] = pb[j];
    }
    float4 ppre[2];
    {
        const float4* gw = (const float4*)proj_w;
        #pragma unroll
        for (int q = 0; q < 2; ++q) ppre[q] = gw[tid + 256 * q];
    }

    for (int c = 0; c < 8; ++c) {
        {
            float4* swb4 = (float4*)swb;
            #pragma unroll
            for (int q = 0; q < 2; ++q) swb4[tid + 256 * q] = ppre[q];
        }
        __syncthreads();
        if (c < 7) {
            const float4* gw = (const float4*)(proj_w + (c + 1) * 16 * 128);
            #pragma unroll
            for (int q = 0; q < 2; ++q) ppre[q] = gw[tid + 256 * q];
        }
        const int kc = c * 16;
        #pragma unroll 4
        for (int k = 0; k < 16; ++k) {
            float xv[7];
            #pragma unroll
            for (int i = 0; i < 7; ++i) {
                int r = ty + 8 * i; r = (r < WIN_N) ? r : (WIN_N - 1);
                xv[i] = sx[r * DIMC + kc + k];
            }
            float wv[4];
            #pragma unroll
            for (int j = 0; j < 4; ++j) wv[j] = swb[k * 128 + tx + 32 * j];
            #pragma unroll
            for (int i = 0; i < 7; ++i)
                #pragma unroll
                for (int j = 0; j < 4; ++j) pacc[i][j] += xv[i] * wv[j];
        }
        __syncthreads();
    }

    // ---------------- store ----------------
    {
        float* go = out + (size_t)b * (WIN_N * DIMC);
        #pragma unroll
        for (int i = 0; i < 7; ++i) {
            int r = ty + 8 * i;
            if (r < WIN_N) {
                #pragma unroll
                for (int j = 0; j < 4; ++j)
                    go[r * DIMC + tx + 32 * j] = pacc[i][j];
            }
        }
    }
}

extern "C" void kernel_launch(void* const* d_in, const int* in_sizes, int n_in,
                              void* d_out, int out_size)
{
    const float* x       = (const float*)d_in[0];
    const float* mask    = (const float*)d_in[1];
    const float* qkv_w   = (const float*)d_in[2];
    const float* qkv_b   = (const float*)d_in[3];
    const float* proj_w  = (const float*)d_in[4];
    const float* proj_b  = (const float*)d_in[5];
    const float* table   = (const float*)d_in[6];
    const int*   relidx  = (const int*)d_in[7];
    float*       out     = (float*)d_out;

    const int B  = in_sizes[0] / (WIN_N * DIMC);   // 4096 windows
    const int nW = in_sizes[1] / (WIN_N * WIN_N);  // 64 mask windows

    cudaFuncSetAttribute(win_attn_kernel,
                         cudaFuncAttributeMaxDynamicSharedMemorySize, SMEM_BYTES);
    win_attn_kernel<<<B, 256, SMEM_BYTES>>>(x, mask, qkv_w, qkv_b,
                                            proj_w, proj_b, table, relidx,
                                            out, nW);
}

// round 2
// speedup vs baseline: 1.3293x; 1.3293x over previous
#include <cuda_runtime.h>

#define WIN_N 49
#define DIMC  128
#define NH    4
#define HD    32
#define QSCALE 0.17677669529663687f  /* 32^-0.5 */
#define KTS   57                      /* skT j-stride (odd: fewer bank conflicts) */

// ---- dynamic smem layout (floats) ----
// sx   [49*128]   = 6272  (x; reused as v after QKV GEMM)
// swb  [2*8*384]  = 6144  (double-buffered weight chunks; proj uses 2*16*128)
// sq   [49*128]   = 6272  (q scaled; reused as attention output)
// skT  [4*32*57]  = 7296  (k transposed [h][d][j])
// total 25984 floats = 103936 B  -> 2 CTAs / SM
#define OFF_SX  0
#define OFF_SWB 6272
#define OFF_SQ  12416
#define OFF_SKT 18688
#define SMEM_FLOATS 25984
#define SMEM_BYTES  (SMEM_FLOATS * 4)

__device__ __forceinline__ void cp16(unsigned dst, const float* src) {
    asm volatile("cp.async.cg.shared.global [%0], [%1], 16;" :: "r"(dst), "l"(src));
}
__device__ __forceinline__ void cp_commit() { asm volatile("cp.async.commit_group;"); }
__device__ __forceinline__ void cp_wait1()  { asm volatile("cp.async.wait_group 1;"); }
__device__ __forceinline__ void cp_wait0()  { asm volatile("cp.async.wait_group 0;"); }

__global__ __launch_bounds__(256, 2)
void win_attn_kernel(const float* __restrict__ x,
                     const float* __restrict__ mask,
                     const float* __restrict__ qkv_w,
                     const float* __restrict__ qkv_b,
                     const float* __restrict__ proj_w,
                     const float* __restrict__ proj_b,
                     const float* __restrict__ bias_table,
                     const int*   __restrict__ rel_index,
                     float* __restrict__ out,
                     int nW)
{
    extern __shared__ float sm[];
    float* sx  = sm + OFF_SX;
    float* swb = sm + OFF_SWB;
    float* sq  = sm + OFF_SQ;
    float* skT = sm + OFF_SKT;
    const unsigned swb_sa = (unsigned)__cvta_generic_to_shared(swb);

    const int b   = blockIdx.x;
    const int tid = threadIdx.x;
    const int tx  = tid & 31;
    const int ty  = tid >> 5;

    // ---- prologue: async-load QKV weight chunks 0,1 (8 rows x 384 each) ----
    {
        const float* src = qkv_w + tid * 4;
        unsigned dst = swb_sa + tid * 16;
        cp16(dst, src); cp16(dst + 4096, src + 1024); cp16(dst + 8192, src + 2048);
        cp_commit();
        src += 3072; dst += 3072 * 4;
        cp16(dst, src); cp16(dst + 4096, src + 1024); cp16(dst + 8192, src + 2048);
        cp_commit();
    }

    // ---- load x window [49,128] ----
    {
        const float4* gx  = (const float4*)(x + (size_t)b * (WIN_N * DIMC));
        float4*       sx4 = (float4*)sx;
        #pragma unroll
        for (int i = 0; i < 7; ++i) {
            int idx = tid + 256 * i;
            if (idx < (WIN_N * DIMC / 4)) sx4[idx] = gx[idx];
        }
    }

    // ---- QKV GEMM: [49,128] @ [128,384] + b ----
    // thread tile: rows r = ty + 8*i (i<7), cols 4*tx + 128*j (j<3, float4)
    float4 acc[7][3];
    {
        #pragma unroll
        for (int j = 0; j < 3; ++j) {
            float4 bb = *(const float4*)(qkv_b + 4 * tx + 128 * j);
            #pragma unroll
            for (int i = 0; i < 7; ++i) acc[i][j] = bb;
        }
    }

    for (int c = 0; c < 16; ++c) {
        if (c < 15) cp_wait1(); else cp_wait0();
        __syncthreads();
        const float* wb = swb + (c & 1) * 3072;
        const int kc = c * 8;
        #pragma unroll
        for (int k = 0; k < 8; ++k) {
            float xv[7];
            #pragma unroll
            for (int i = 0; i < 7; ++i) {
                int r = ty + 8 * i; r = (r < WIN_N) ? r : (WIN_N - 1);
                xv[i] = sx[r * DIMC + kc + k];          // warp-broadcast
            }
            float4 wv[3];
            #pragma unroll
            for (int j = 0; j < 3; ++j)
                wv[j] = *(const float4*)(wb + k * 384 + 4 * tx + 128 * j);
            #pragma unroll
            for (int i = 0; i < 7; ++i)
                #pragma unroll
                for (int j = 0; j < 3; ++j) {
                    acc[i][j].x += xv[i] * wv[j].x;
                    acc[i][j].y += xv[i] * wv[j].y;
                    acc[i][j].z += xv[i] * wv[j].z;
                    acc[i][j].w += xv[i] * wv[j].w;
                }
        }
        __syncthreads();
        if (c + 2 < 16) {   // refill the buffer just consumed
            const float* src = qkv_w + (c + 2) * 3072 + tid * 4;
            unsigned dst = swb_sa + ((c & 1) * 3072 + tid * 4) * 4;
            cp16(dst, src); cp16(dst + 4096, src + 1024); cp16(dst + 8192, src + 2048);
            cp_commit();
        }
    }

    // ---- scatter: q (scaled) -> sq, k -> skT (transposed), v -> sx ----
    #pragma unroll
    for (int i = 0; i < 7; ++i) {
        int r = ty + 8 * i;
        if (r < WIN_N) {
            float4 qv = acc[i][0];
            qv.x *= QSCALE; qv.y *= QSCALE; qv.z *= QSCALE; qv.w *= QSCALE;
            *(float4*)(sq + r * DIMC + 4 * tx) = qv;
            #pragma unroll
            for (int e = 0; e < 4; ++e) {
                int cc = 4 * tx + e;
                float kv = (&acc[i][1].x)[e];
                skT[(cc >> 5) * (HD * KTS) + (cc & 31) * KTS + r] = kv;
            }
            *(float4*)(sx + r * DIMC + 4 * tx) = acc[i][2];   // v over x
        }
    }

    // prefetch proj weight chunks 0,1 (16 rows x 128 each) while attention runs
    {
        const float* src = proj_w + tid * 4;
        unsigned dst = swb_sa + tid * 16;
        cp16(dst, src); cp16(dst + 4096, src + 1024);
        cp_commit();
        src += 2048; dst += 2048 * 4;
        cp16(dst, src); cp16(dst + 4096, src + 1024);
        cp_commit();
    }
    __syncthreads();

    // ---- attention: 2 warps per head, 2 rows per iteration ----
    {
        const int h = ty >> 1, sub = ty & 1, lane = tx;
        const float* masks = mask + (size_t)(b & (nW - 1)) * (WIN_N * WIN_N);
        const float* kt = skT + h * (HD * KTS);
        const float* vb = sx + h * HD + lane;   // v column base
        const int j1 = lane + 32;
        const bool vj1 = (j1 < WIN_N);
        const int j1c = vj1 ? j1 : 0;

        for (int t = 0; t < 13; ++t) {
            int i0 = 4 * t + 2 * sub;
            if (i0 >= WIN_N) break;
            int i1 = i0 + 1;
            bool two = (i1 < WIN_N);
            int r1 = two ? i1 : i0;

            // gathers issued early
            int idx00 = rel_index[i0 * WIN_N + lane];
            int idx01 = rel_index[i0 * WIN_N + j1c];
            int idx10 = rel_index[r1 * WIN_N + lane];
            int idx11 = rel_index[r1 * WIN_N + j1c];
            float m00 = masks[i0 * WIN_N + lane], m01 = masks[i0 * WIN_N + j1c];
            float m10 = masks[r1 * WIN_N + lane], m11 = masks[r1 * WIN_N + j1c];

            const float* q0 = sq + i0 * DIMC + h * HD;
            const float* q1 = sq + r1 * DIMC + h * HD;
            float a00 = 0.f, a01 = 0.f, a10 = 0.f, a11 = 0.f;
            #pragma unroll
            for (int d = 0; d < HD; ++d) {
                float k0 = kt[d * KTS + lane];
                float k1 = kt[d * KTS + j1c];
                float qa = q0[d], qb = q1[d];
                a00 += qa * k0; a01 += qa * k1;
                a10 += qb * k0; a11 += qb * k1;
            }
            a00 += bias_table[idx00 * NH + h] + m00;
            a01 = vj1 ? (a01 + bias_table[idx01 * NH + h] + m01) : -1e30f;
            a10 += bias_table[idx10 * NH + h] + m10;
            a11 = vj1 ? (a11 + bias_table[idx11 * NH + h] + m11) : -1e30f;

            float mx0 = fmaxf(a00, a01), mx1 = fmaxf(a10, a11);
            #pragma unroll
            for (int o = 16; o > 0; o >>= 1) {
                mx0 = fmaxf(mx0, __shfl_xor_sync(0xffffffffu, mx0, o));
                mx1 = fmaxf(mx1, __shfl_xor_sync(0xffffffffu, mx1, o));
            }
            float e00 = __expf(a00 - mx0), e01 = vj1 ? __expf(a01 - mx0) : 0.f;
            float e10 = __expf(a10 - mx1), e11 = vj1 ? __expf(a11 - mx1) : 0.f;
            float s0 = e00 + e01, s1 = e10 + e11;
            #pragma unroll
            for (int o = 16; o > 0; o >>= 1) {
                s0 += __shfl_xor_sync(0xffffffffu, s0, o);
                s1 += __shfl_xor_sync(0xffffffffu, s1, o);
            }
            float p00 = e00 / s0, p01 = e01 / s0;
            float p10 = e10 / s1, p11 = e11 / s1;

            // attn @ v via shuffle broadcast (no smem attn matrix)
            float o0a = 0.f, o0b = 0.f, o1a = 0.f, o1b = 0.f;
            #pragma unroll
            for (int j = 0; j < 32; j += 2) {
                float va = vb[j * DIMC], vc2 = vb[(j + 1) * DIMC];
                float pa0 = __shfl_sync(0xffffffffu, p00, j);
                float pb0 = __shfl_sync(0xffffffffu, p00, j + 1);
                float pa1 = __shfl_sync(0xffffffffu, p10, j);
                float pb1 = __shfl_sync(0xffffffffu, p10, j + 1);
                o0a += pa0 * va; o0b += pb0 * vc2;
                o1a += pa1 * va; o1b += pb1 * vc2;
            }
            #pragma unroll
            for (int j = 0; j < 16; j += 2) {
                float va = vb[(32 + j) * DIMC], vc2 = vb[(33 + j) * DIMC];
                float pa0 = __shfl_sync(0xffffffffu, p01, j);
                float pb0 = __shfl_sync(0xffffffffu, p01, j + 1);
                float pa1 = __shfl_sync(0xffffffffu, p11, j);
                float pb1 = __shfl_sync(0xffffffffu, p11, j + 1);
                o0a += pa0 * va; o0b += pb0 * vc2;
                o1a += pa1 * va; o1b += pb1 * vc2;
            }
            {   // j = 48
                float va = vb[48 * DIMC];
                float pa0 = __shfl_sync(0xffffffffu, p01, 16);
                float pa1 = __shfl_sync(0xffffffffu, p11, 16);
                o0a += pa0 * va;
                o1a += pa1 * va;
            }
            // write attention output over the q rows we just consumed
            sq[i0 * DIMC + h * HD + lane] = o0a + o0b;
            if (two) sq[i1 * DIMC + h * HD + lane] = o1a + o1b;
        }
    }
    __syncthreads();

    // ---- proj GEMM: [49,128] @ [128,128] + b  (reads attn out from sq) ----
    float4 pacc[7];
    {
        float4 pb = *(const float4*)(proj_b + 4 * tx);
        #pragma unroll
        for (int i = 0; i < 7; ++i) pacc[i] = pb;
    }

    for (int c = 0; c < 8; ++c) {
        if (c < 7) cp_wait1(); else cp_wait0();
        __syncthreads();
        const float* wb = swb + (c & 1) * 2048;
        const int kc = c * 16;
        #pragma unroll
        for (int k = 0; k < 16; ++k) {
            float xv[7];
            #pragma unroll
            for (int i = 0; i < 7; ++i) {
                int r = ty + 8 * i; r = (r < WIN_N) ? r : (WIN_N - 1);
                xv[i] = sq[r * DIMC + kc + k];
            }
            float4 wv = *(const float4*)(wb + k * DIMC + 4 * tx);
            #pragma unroll
            for (int i = 0; i < 7; ++i) {
                pacc[i].x += xv[i] * wv.x;
                pacc[i].y += xv[i] * wv.y;
                pacc[i].z += xv[i] * wv.z;
                pacc[i].w += xv[i] * wv.w;
            }
        }
        __syncthreads();
        if (c + 2 < 8) {
            const float* src = proj_w + (c + 2) * 2048 + tid * 4;
            unsigned dst = swb_sa + ((c & 1) * 2048 + tid * 4) * 4;
            cp16(dst, src); cp16(dst + 4096, src + 1024);
            cp_commit();
        }
    }

    // ---- store ----
    {
        float* go = out + (size_t)b * (WIN_N * DIMC);
        #pragma unroll
        for (int i = 0; i < 7; ++i) {
            int r = ty + 8 * i;
            if (r < WIN_N)
                *(float4*)(go + r * DIMC + 4 * tx) = pacc[i];
        }
    }
}

extern "C" void kernel_launch(void* const* d_in, const int* in_sizes, int n_in,
                              void* d_out, int out_size)
{
    const float* x      = (const float*)d_in[0];
    const float* mask   = (const float*)d_in[1];
    const float* qkv_w  = (const float*)d_in[2];
    const float* qkv_b  = (const float*)d_in[3];
    const float* proj_w = (const float*)d_in[4];
    const float* proj_b = (const float*)d_in[5];
    const float* table  = (const float*)d_in[6];
    const int*   relidx = (const int*)d_in[7];
    float*       out    = (float*)d_out;

    const int B  = in_sizes[0] / (WIN_N * DIMC);
    const int nW = in_sizes[1] / (WIN_N * WIN_N);

    cudaFuncSetAttribute(win_attn_kernel,
                         cudaFuncAttributeMaxDynamicSharedMemorySize, SMEM_BYTES);
    win_attn_kernel<<<B, 256, SMEM_BYTES>>>(x, mask, qkv_w, qkv_b,
                                            proj_w, proj_b, table, relidx,
                                            out, nW);
}

// round 3
// speedup vs baseline: 1.3820x; 1.0396x over previous
#include <cuda_runtime.h>

#define WIN_N 49
#define DIMC  128
#define NH    4
#define HD    32
#define QSCALE 0.17677669529663687f  /* 32^-0.5 */
#define KTS   57                      /* skT j-stride (odd: fewer bank conflicts) */

// ---- dynamic smem layout (floats) ----
// sx   [49*128]   = 6272  (x; reused as v after QKV GEMM)
// swb  [2*8*384]  = 6144  (double-buffered weight chunks; proj uses 2*16*128)
// sq   [49*128]   = 6272  (q scaled; reused as attention output)
// skT  [4*32*57]  = 7296  (k transposed [h][d][j])
// total 25984 floats = 103936 B  -> 2 CTAs / SM
#define OFF_SX  0
#define OFF_SWB 6272
#define OFF_SQ  12416
#define OFF_SKT 18688
#define SMEM_FLOATS 25984
#define SMEM_BYTES  (SMEM_FLOATS * 4)

typedef unsigned long long u64;

__device__ __forceinline__ void cp16(unsigned dst, const float* src) {
    asm volatile("cp.async.cg.shared.global [%0], [%1], 16;" :: "r"(dst), "l"(src));
}
__device__ __forceinline__ void cp_commit() { asm volatile("cp.async.commit_group;"); }
__device__ __forceinline__ void cp_wait1()  { asm volatile("cp.async.wait_group 1;"); }
__device__ __forceinline__ void cp_wait0()  { asm volatile("cp.async.wait_group 0;"); }

// packed fp32x2 FMA: d += a * b  (SASS FFMA2 — 2x fp32 rate vs FFMA-3reg)
__device__ __forceinline__ void ffma2(u64& d, u64 a, u64 b) {
    asm("fma.rn.f32x2 %0, %1, %2, %0;" : "+l"(d) : "l"(a), "l"(b));
}
__device__ __forceinline__ u64 dup2(float v) {
    u64 r; unsigned u = __float_as_uint(v);
    asm("mov.b64 %0, {%1, %1};" : "=l"(r) : "r"(u));
    return r;
}
__device__ __forceinline__ float2 unpk(u64 v) {
    unsigned lo, hi;
    asm("mov.b64 {%0, %1}, %2;" : "=r"(lo), "=r"(hi) : "l"(v));
    return make_float2(__uint_as_float(lo), __uint_as_float(hi));
}

__global__ __launch_bounds__(256, 2)
void win_attn_kernel(const float* __restrict__ x,
                     const float* __restrict__ mask,
                     const float* __restrict__ qkv_w,
                     const float* __restrict__ qkv_b,
                     const float* __restrict__ proj_w,
                     const float* __restrict__ proj_b,
                     const float* __restrict__ bias_table,
                     const int*   __restrict__ rel_index,
                     float* __restrict__ out,
                     int nW)
{
    extern __shared__ float sm[];
    float* sx  = sm + OFF_SX;
    float* swb = sm + OFF_SWB;
    float* sq  = sm + OFF_SQ;
    float* skT = sm + OFF_SKT;
    const unsigned swb_sa = (unsigned)__cvta_generic_to_shared(swb);

    const int b   = blockIdx.x;
    const int tid = threadIdx.x;
    const int tx  = tid & 31;
    const int ty  = tid >> 5;

    // ---- prologue: async-load QKV weight chunks 0,1 (8 rows x 384 each) ----
    {
        const float* src = qkv_w + tid * 4;
        unsigned dst = swb_sa + tid * 16;
        cp16(dst, src); cp16(dst + 4096, src + 1024); cp16(dst + 8192, src + 2048);
        cp_commit();
        src += 3072; dst += 3072 * 4;
        cp16(dst, src); cp16(dst + 4096, src + 1024); cp16(dst + 8192, src + 2048);
        cp_commit();
    }

    // ---- load x window [49,128] ----
    {
        const float4* gx  = (const float4*)(x + (size_t)b * (WIN_N * DIMC));
        float4*       sx4 = (float4*)sx;
        #pragma unroll
        for (int i = 0; i < 7; ++i) {
            int idx = tid + 256 * i;
            if (idx < (WIN_N * DIMC / 4)) sx4[idx] = gx[idx];
        }
    }

    // ---- QKV GEMM: [49,128] @ [128,384] + b  (packed f32x2) ----
    // thread tile: rows r = ty + 8*i (i<7), col pairs (4*tx + 128*j) .. +3
    u64 acc2[7][6];
    {
        #pragma unroll
        for (int j = 0; j < 3; ++j) {
            ulonglong2 bb = *(const ulonglong2*)(qkv_b + 4 * tx + 128 * j);
            #pragma unroll
            for (int i = 0; i < 7; ++i) { acc2[i][2*j] = bb.x; acc2[i][2*j+1] = bb.y; }
        }
    }

    for (int c = 0; c < 16; ++c) {
        if (c < 15) cp_wait1(); else cp_wait0();
        __syncthreads();
        const float* wb = swb + (c & 1) * 3072;
        const int kc = c * 8;
        #pragma unroll
        for (int k2 = 0; k2 < 8; k2 += 2) {
            float2 xv2[7];
            #pragma unroll
            for (int i = 0; i < 7; ++i) {
                int r = ty + 8 * i; r = (r < WIN_N) ? r : (WIN_N - 1);
                xv2[i] = *(const float2*)(sx + r * DIMC + kc + k2);  // 8B broadcast
            }
            #pragma unroll
            for (int s = 0; s < 2; ++s) {
                const int k = k2 + s;
                u64 xp[7];
                #pragma unroll
                for (int i = 0; i < 7; ++i) xp[i] = dup2(s ? xv2[i].y : xv2[i].x);
                ulonglong2 wv[3];
                #pragma unroll
                for (int j = 0; j < 3; ++j)
                    wv[j] = *(const ulonglong2*)(wb + k * 384 + 4 * tx + 128 * j);
                #pragma unroll
                for (int i = 0; i < 7; ++i)
                    #pragma unroll
                    for (int j = 0; j < 3; ++j) {
                        ffma2(acc2[i][2*j],   xp[i], wv[j].x);
                        ffma2(acc2[i][2*j+1], xp[i], wv[j].y);
                    }
            }
        }
        __syncthreads();
        if (c + 2 < 16) {   // refill the buffer just consumed
            const float* src = qkv_w + (c + 2) * 3072 + tid * 4;
            unsigned dst = swb_sa + ((c & 1) * 3072 + tid * 4) * 4;
            cp16(dst, src); cp16(dst + 4096, src + 1024); cp16(dst + 8192, src + 2048);
            cp_commit();
        }
    }

    // ---- scatter: q (scaled) -> sq, k -> skT (transposed), v -> sx ----
    #pragma unroll
    for (int i = 0; i < 7; ++i) {
        int r = ty + 8 * i;
        if (r < WIN_N) {
            float2 q01 = unpk(acc2[i][0]), q23 = unpk(acc2[i][1]);
            float4 qv = make_float4(q01.x * QSCALE, q01.y * QSCALE,
                                    q23.x * QSCALE, q23.y * QSCALE);
            *(float4*)(sq + r * DIMC + 4 * tx) = qv;

            float2 k01 = unpk(acc2[i][2]), k23 = unpk(acc2[i][3]);
            float kf[4] = {k01.x, k01.y, k23.x, k23.y};
            #pragma unroll
            for (int e = 0; e < 4; ++e) {
                int cc = 4 * tx + e;
                skT[(cc >> 5) * (HD * KTS) + (cc & 31) * KTS + r] = kf[e];
            }

            float2 v01 = unpk(acc2[i][4]), v23 = unpk(acc2[i][5]);
            *(float4*)(sx + r * DIMC + 4 * tx) =
                make_float4(v01.x, v01.y, v23.x, v23.y);   // v over x
        }
    }

    // prefetch proj weight chunks 0,1 (16 rows x 128 each) while attention runs
    {
        const float* src = proj_w + tid * 4;
        unsigned dst = swb_sa + tid * 16;
        cp16(dst, src); cp16(dst + 4096, src + 1024);
        cp_commit();
        src += 2048; dst += 2048 * 4;
        cp16(dst, src); cp16(dst + 4096, src + 1024);
        cp_commit();
    }
    __syncthreads();

    // ---- attention: 2 warps per head, 2 rows per iteration ----
    {
        const int h = ty >> 1, sub = ty & 1, lane = tx;
        const float* masks = mask + (size_t)(b & (nW - 1)) * (WIN_N * WIN_N);
        const float* kt = skT + h * (HD * KTS);
        const float* vb = sx + h * HD + lane;   // v column base
        const int j1 = lane + 32;
        const bool vj1 = (j1 < WIN_N);
        const int j1c = vj1 ? j1 : 0;

        for (int t = 0; t < 13; ++t) {
            int i0 = 4 * t + 2 * sub;
            if (i0 >= WIN_N) break;
            int i1 = i0 + 1;
            bool two = (i1 < WIN_N);
            int r1 = two ? i1 : i0;

            // gathers issued early
            int idx00 = rel_index[i0 * WIN_N + lane];
            int idx01 = rel_index[i0 * WIN_N + j1c];
            int idx10 = rel_index[r1 * WIN_N + lane];
            int idx11 = rel_index[r1 * WIN_N + j1c];
            float m00 = masks[i0 * WIN_N + lane], m01 = masks[i0 * WIN_N + j1c];
            float m10 = masks[r1 * WIN_N + lane], m11 = masks[r1 * WIN_N + j1c];

            const float* q0 = sq + i0 * DIMC + h * HD;
            const float* q1 = sq + r1 * DIMC + h * HD;
            float a00 = 0.f, a01 = 0.f, a10 = 0.f, a11 = 0.f;
            #pragma unroll
            for (int d = 0; d < HD; ++d) {
                float k0 = kt[d * KTS + lane];
                float k1 = kt[d * KTS + j1c];
                float qa = q0[d], qb = q1[d];
                a00 += qa * k0; a01 += qa * k1;
                a10 += qb * k0; a11 += qb * k1;
            }
            a00 += bias_table[idx00 * NH + h] + m00;
            a01 = vj1 ? (a01 + bias_table[idx01 * NH + h] + m01) : -1e30f;
            a10 += bias_table[idx10 * NH + h] + m10;
            a11 = vj1 ? (a11 + bias_table[idx11 * NH + h] + m11) : -1e30f;

            float mx0 = fmaxf(a00, a01), mx1 = fmaxf(a10, a11);
            #pragma unroll
            for (int o = 16; o > 0; o >>= 1) {
                mx0 = fmaxf(mx0, __shfl_xor_sync(0xffffffffu, mx0, o));
                mx1 = fmaxf(mx1, __shfl_xor_sync(0xffffffffu, mx1, o));
            }
            float e00 = __expf(a00 - mx0), e01 = vj1 ? __expf(a01 - mx0) : 0.f;
            float e10 = __expf(a10 - mx1), e11 = vj1 ? __expf(a11 - mx1) : 0.f;
            float s0 = e00 + e01, s1 = e10 + e11;
            #pragma unroll
            for (int o = 16; o > 0; o >>= 1) {
                s0 += __shfl_xor_sync(0xffffffffu, s0, o);
                s1 += __shfl_xor_sync(0xffffffffu, s1, o);
            }
            float p00 = e00 / s0, p01 = e01 / s0;
            float p10 = e10 / s1, p11 = e11 / s1;

            // attn @ v via shuffle broadcast (no smem attn matrix)
            float o0a = 0.f, o0b = 0.f, o1a = 0.f, o1b = 0.f;
            #pragma unroll
            for (int j = 0; j < 32; j += 2) {
                float va = vb[j * DIMC], vc2 = vb[(j + 1) * DIMC];
                float pa0 = __shfl_sync(0xffffffffu, p00, j);
                float pb0 = __shfl_sync(0xffffffffu, p00, j + 1);
                float pa1 = __shfl_sync(0xffffffffu, p10, j);
                float pb1 = __shfl_sync(0xffffffffu, p10, j + 1);
                o0a += pa0 * va; o0b += pb0 * vc2;
                o1a += pa1 * va; o1b += pb1 * vc2;
            }
            #pragma unroll
            for (int j = 0; j < 16; j += 2) {
                float va = vb[(32 + j) * DIMC], vc2 = vb[(33 + j) * DIMC];
                float pa0 = __shfl_sync(0xffffffffu, p01, j);
                float pb0 = __shfl_sync(0xffffffffu, p01, j + 1);
                float pa1 = __shfl_sync(0xffffffffu, p11, j);
                float pb1 = __shfl_sync(0xffffffffu, p11, j + 1);
                o0a += pa0 * va; o0b += pb0 * vc2;
                o1a += pa1 * va; o1b += pb1 * vc2;
            }
            {   // j = 48
                float va = vb[48 * DIMC];
                float pa0 = __shfl_sync(0xffffffffu, p01, 16);
                float pa1 = __shfl_sync(0xffffffffu, p11, 16);
                o0a += pa0 * va;
                o1a += pa1 * va;
            }
            // write attention output over the q rows we just consumed
            sq[i0 * DIMC + h * HD + lane] = o0a + o0b;
            if (two) sq[i1 * DIMC + h * HD + lane] = o1a + o1b;
        }
    }
    __syncthreads();

    // ---- proj GEMM: [49,128] @ [128,128] + b  (packed f32x2) ----
    u64 pacc2[7][2];
    {
        ulonglong2 pb = *(const ulonglong2*)(proj_b + 4 * tx);
        #pragma unroll
        for (int i = 0; i < 7; ++i) { pacc2[i][0] = pb.x; pacc2[i][1] = pb.y; }
    }

    for (int c = 0; c < 8; ++c) {
        if (c < 7) cp_wait1(); else cp_wait0();
        __syncthreads();
        const float* wb = swb + (c & 1) * 2048;
        const int kc = c * 16;
        #pragma unroll
        for (int k2 = 0; k2 < 16; k2 += 2) {
            float2 xv2[7];
            #pragma unroll
            for (int i = 0; i < 7; ++i) {
                int r = ty + 8 * i; r = (r < WIN_N) ? r : (WIN_N - 1);
                xv2[i] = *(const float2*)(sq + r * DIMC + kc + k2);
            }
            #pragma unroll
            for (int s = 0; s < 2; ++s) {
                const int k = k2 + s;
                ulonglong2 wv = *(const ulonglong2*)(wb + k * DIMC + 4 * tx);
                #pragma unroll
                for (int i = 0; i < 7; ++i) {
                    u64 xp = dup2(s ? xv2[i].y : xv2[i].x);
                    ffma2(pacc2[i][0], xp, wv.x);
                    ffma2(pacc2[i][1], xp, wv.y);
                }
            }
        }
        __syncthreads();
        if (c + 2 < 8) {
            const float* src = proj_w + (c + 2) * 2048 + tid * 4;
            unsigned dst = swb_sa + ((c & 1) * 2048 + tid * 4) * 4;
            cp16(dst, src); cp16(dst + 4096, src + 1024);
            cp_commit();
        }
    }

    // ---- store ----
    {
        float* go = out + (size_t)b * (WIN_N * DIMC);
        #pragma unroll
        for (int i = 0; i < 7; ++i) {
            int r = ty + 8 * i;
            if (r < WIN_N) {
                float2 a = unpk(pacc2[i][0]), c2 = unpk(pacc2[i][1]);
                *(float4*)(go + r * DIMC + 4 * tx) = make_float4(a.x, a.y, c2.x, c2.y);
            }
        }
    }
}

extern "C" void kernel_launch(void* const* d_in, const int* in_sizes, int n_in,
                              void* d_out, int out_size)
{
    const float* x      = (const float*)d_in[0];
    const float* mask   = (const float*)d_in[1];
    const float* qkv_w  = (const float*)d_in[2];
    const float* qkv_b  = (const float*)d_in[3];
    const float* proj_w = (const float*)d_in[4];
    const float* proj_b = (const float*)d_in[5];
    const float* table  = (const float*)d_in[6];
    const int*   relidx = (const int*)d_in[7];
    float*       out    = (float*)d_out;

    const int B  = in_sizes[0] / (WIN_N * DIMC);
    const int nW = in_sizes[1] / (WIN_N * WIN_N);

    cudaFuncSetAttribute(win_attn_kernel,
                         cudaFuncAttributeMaxDynamicSharedMemorySize, SMEM_BYTES);
    win_attn_kernel<<<B, 256, SMEM_BYTES>>>(x, mask, qkv_w, qkv_b,
                                            proj_w, proj_b, table, relidx,
                                            out, nW);
}

// round 4
// speedup vs baseline: 1.3835x; 1.0011x over previous
#include <cuda_runtime.h>

#define WIN_N 49
#define DIMC  128
#define NH    4
#define HD    32
#define QSCALE 0.17677669529663687f  /* 32^-0.5 */
#define KTS   57                      /* skT j-stride (odd: fewer bank conflicts) */

// ---- dynamic smem layout (floats) ----
// sx   [49*128]   = 6272  (x; reused as v after QKV GEMM)
// swb  [2*8*384]  = 6144  (double-buffered weight chunks; proj uses 2*16*128)
// sq   [49*128]   = 6272  (q scaled; reused as attention output)
// skT  [4*32*57]  = 7296  (k transposed [h][d][j])
// total 25984 floats = 103936 B  -> 2 CTAs / SM
#define OFF_SX  0
#define OFF_SWB 6272
#define OFF_SQ  12416
#define OFF_SKT 18688
#define SMEM_FLOATS 25984
#define SMEM_BYTES  (SMEM_FLOATS * 4)

typedef unsigned long long u64;

__device__ __forceinline__ void cp16(unsigned dst, const float* src) {
    asm volatile("cp.async.cg.shared.global [%0], [%1], 16;" :: "r"(dst), "l"(src));
}
__device__ __forceinline__ void cp_commit() { asm volatile("cp.async.commit_group;"); }
__device__ __forceinline__ void cp_wait1()  { asm volatile("cp.async.wait_group 1;"); }
__device__ __forceinline__ void cp_wait0()  { asm volatile("cp.async.wait_group 0;"); }

// packed fp32x2 FMA: d += a * b  (SASS FFMA2 — 2x fp32 rate vs FFMA-3reg)
__device__ __forceinline__ void ffma2(u64& d, u64 a, u64 b) {
    asm("fma.rn.f32x2 %0, %1, %2, %0;" : "+l"(d) : "l"(a), "l"(b));
}
__device__ __forceinline__ u64 dup2(float v) {
    u64 r; unsigned u = __float_as_uint(v);
    asm("mov.b64 %0, {%1, %1};" : "=l"(r) : "r"(u));
    return r;
}
__device__ __forceinline__ float2 unpk(u64 v) {
    unsigned lo, hi;
    asm("mov.b64 {%0, %1}, %2;" : "=r"(lo), "=r"(hi) : "l"(v));
    return make_float2(__uint_as_float(lo), __uint_as_float(hi));
}

__global__ __launch_bounds__(256, 2)
void win_attn_kernel(const float* __restrict__ x,
                     const float* __restrict__ mask,
                     const float* __restrict__ qkv_w,
                     const float* __restrict__ qkv_b,
                     const float* __restrict__ proj_w,
                     const float* __restrict__ proj_b,
                     const float* __restrict__ bias_table,
                     const int*   __restrict__ rel_index,
                     float* __restrict__ out,
                     int nW)
{
    extern __shared__ float sm[];
    float* sx  = sm + OFF_SX;
    float* swb = sm + OFF_SWB;
    float* sq  = sm + OFF_SQ;
    float* skT = sm + OFF_SKT;
    const unsigned swb_sa = (unsigned)__cvta_generic_to_shared(swb);

    const int b   = blockIdx.x;
    const int tid = threadIdx.x;
    const int tx  = tid & 31;
    const int ty  = tid >> 5;

    // ---- prologue: async-load QKV weight chunks 0,1 (8 rows x 384 each) ----
    {
        const float* src = qkv_w + tid * 4;
        unsigned dst = swb_sa + tid * 16;
        cp16(dst, src); cp16(dst + 4096, src + 1024); cp16(dst + 8192, src + 2048);
        cp_commit();
        src += 3072; dst += 3072 * 4;
        cp16(dst, src); cp16(dst + 4096, src + 1024); cp16(dst + 8192, src + 2048);
        cp_commit();
    }

    // ---- load x window [49,128] ----
    {
        const float4* gx  = (const float4*)(x + (size_t)b * (WIN_N * DIMC));
        float4*       sx4 = (float4*)sx;
        #pragma unroll
        for (int i = 0; i < 7; ++i) {
            int idx = tid + 256 * i;
            if (idx < (WIN_N * DIMC / 4)) sx4[idx] = gx[idx];
        }
    }

    // ---- QKV GEMM: [49,128] @ [128,384] + b  (packed f32x2) ----
    // thread tile: rows r = ty + 8*i (i<7), col pairs (4*tx + 128*j) .. +3
    u64 acc2[7][6];
    {
        #pragma unroll
        for (int j = 0; j < 3; ++j) {
            ulonglong2 bb = *(const ulonglong2*)(qkv_b + 4 * tx + 128 * j);
            #pragma unroll
            for (int i = 0; i < 7; ++i) { acc2[i][2*j] = bb.x; acc2[i][2*j+1] = bb.y; }
        }
    }

    for (int c = 0; c < 16; ++c) {
        if (c < 15) cp_wait1(); else cp_wait0();
        __syncthreads();
        const float* wb = swb + (c & 1) * 3072;
        const int kc = c * 8;
        #pragma unroll
        for (int k2 = 0; k2 < 8; k2 += 2) {
            float2 xv2[7];
            #pragma unroll
            for (int i = 0; i < 7; ++i) {
                int r = ty + 8 * i; r = (r < WIN_N) ? r : (WIN_N - 1);
                xv2[i] = *(const float2*)(sx + r * DIMC + kc + k2);  // 8B broadcast
            }
            #pragma unroll
            for (int s = 0; s < 2; ++s) {
                const int k = k2 + s;
                u64 xp[7];
                #pragma unroll
                for (int i = 0; i < 7; ++i) xp[i] = dup2(s ? xv2[i].y : xv2[i].x);
                ulonglong2 wv[3];
                #pragma unroll
                for (int j = 0; j < 3; ++j)
                    wv[j] = *(const ulonglong2*)(wb + k * 384 + 4 * tx + 128 * j);
                #pragma unroll
                for (int i = 0; i < 7; ++i)
                    #pragma unroll
                    for (int j = 0; j < 3; ++j) {
                        ffma2(acc2[i][2*j],   xp[i], wv[j].x);
                        ffma2(acc2[i][2*j+1], xp[i], wv[j].y);
                    }
            }
        }
        __syncthreads();
        if (c + 2 < 16) {   // refill the buffer just consumed
            const float* src = qkv_w + (c + 2) * 3072 + tid * 4;
            unsigned dst = swb_sa + ((c & 1) * 3072 + tid * 4) * 4;
            cp16(dst, src); cp16(dst + 4096, src + 1024); cp16(dst + 8192, src + 2048);
            cp_commit();
        }
    }

    // ---- scatter: q (scaled) -> sq, k -> skT (transposed), v -> sx ----
    #pragma unroll
    for (int i = 0; i < 7; ++i) {
        int r = ty + 8 * i;
        if (r < WIN_N) {
            float2 q01 = unpk(acc2[i][0]), q23 = unpk(acc2[i][1]);
            float4 qv = make_float4(q01.x * QSCALE, q01.y * QSCALE,
                                    q23.x * QSCALE, q23.y * QSCALE);
            *(float4*)(sq + r * DIMC + 4 * tx) = qv;

            float2 k01 = unpk(acc2[i][2]), k23 = unpk(acc2[i][3]);
            float kf[4] = {k01.x, k01.y, k23.x, k23.y};
            #pragma unroll
            for (int e = 0; e < 4; ++e) {
                int cc = 4 * tx + e;
                skT[(cc >> 5) * (HD * KTS) + (cc & 31) * KTS + r] = kf[e];
            }

            float2 v01 = unpk(acc2[i][4]), v23 = unpk(acc2[i][5]);
            *(float4*)(sx + r * DIMC + 4 * tx) =
                make_float4(v01.x, v01.y, v23.x, v23.y);   // v over x
        }
    }

    // prefetch proj weight chunks 0,1 (16 rows x 128 each) while attention runs
    {
        const float* src = proj_w + tid * 4;
        unsigned dst = swb_sa + tid * 16;
        cp16(dst, src); cp16(dst + 4096, src + 1024);
        cp_commit();
        src += 2048; dst += 2048 * 4;
        cp16(dst, src); cp16(dst + 4096, src + 1024);
        cp_commit();
    }
    __syncthreads();

    // ---- attention: 2 warps per head, 2 rows per iteration ----
    {
        const int h = ty >> 1, sub = ty & 1, lane = tx;
        const float* masks = mask + (size_t)(b & (nW - 1)) * (WIN_N * WIN_N);
        const float* kt = skT + h * (HD * KTS);
        const float* vb = sx + h * HD + lane;   // v column base
        const int j1 = lane + 32;
        const bool vj1 = (j1 < WIN_N);
        const int j1c = vj1 ? j1 : 0;

        for (int t = 0; t < 13; ++t) {
            int i0 = 4 * t + 2 * sub;
            if (i0 >= WIN_N) break;
            int i1 = i0 + 1;
            bool two = (i1 < WIN_N);
            int r1 = two ? i1 : i0;

            // gathers issued early
            int idx00 = rel_index[i0 * WIN_N + lane];
            int idx01 = rel_index[i0 * WIN_N + j1c];
            int idx10 = rel_index[r1 * WIN_N + lane];
            int idx11 = rel_index[r1 * WIN_N + j1c];
            float m00 = masks[i0 * WIN_N + lane], m01 = masks[i0 * WIN_N + j1c];
            float m10 = masks[r1 * WIN_N + lane], m11 = masks[r1 * WIN_N + j1c];

            const float* q0 = sq + i0 * DIMC + h * HD;
            const float* q1 = sq + r1 * DIMC + h * HD;
            float a00 = 0.f, a01 = 0.f, a10 = 0.f, a11 = 0.f;
            #pragma unroll
            for (int d = 0; d < HD; ++d) {
                float k0 = kt[d * KTS + lane];
                float k1 = kt[d * KTS + j1c];
                float qa = q0[d], qb = q1[d];
                a00 += qa * k0; a01 += qa * k1;
                a10 += qb * k0; a11 += qb * k1;
            }
            a00 += bias_table[idx00 * NH + h] + m00;
            a01 = vj1 ? (a01 + bias_table[idx01 * NH + h] + m01) : -1e30f;
            a10 += bias_table[idx10 * NH + h] + m10;
            a11 = vj1 ? (a11 + bias_table[idx11 * NH + h] + m11) : -1e30f;

            float mx0 = fmaxf(a00, a01), mx1 = fmaxf(a10, a11);
            #pragma unroll
            for (int o = 16; o > 0; o >>= 1) {
                mx0 = fmaxf(mx0, __shfl_xor_sync(0xffffffffu, mx0, o));
                mx1 = fmaxf(mx1, __shfl_xor_sync(0xffffffffu, mx1, o));
            }
            float e00 = __expf(a00 - mx0), e01 = vj1 ? __expf(a01 - mx0) : 0.f;
            float e10 = __expf(a10 - mx1), e11 = vj1 ? __expf(a11 - mx1) : 0.f;
            float s0 = e00 + e01, s1 = e10 + e11;
            #pragma unroll
            for (int o = 16; o > 0; o >>= 1) {
                s0 += __shfl_xor_sync(0xffffffffu, s0, o);
                s1 += __shfl_xor_sync(0xffffffffu, s1, o);
            }
            float p00 = e00 / s0, p01 = e01 / s0;
            float p10 = e10 / s1, p11 = e11 / s1;

            // attn @ v via shuffle broadcast (no smem attn matrix)
            float o0a = 0.f, o0b = 0.f, o1a = 0.f, o1b = 0.f;
            #pragma unroll
            for (int j = 0; j < 32; j += 2) {
                float va = vb[j * DIMC], vc2 = vb[(j + 1) * DIMC];
                float pa0 = __shfl_sync(0xffffffffu, p00, j);
                float pb0 = __shfl_sync(0xffffffffu, p00, j + 1);
                float pa1 = __shfl_sync(0xffffffffu, p10, j);
                float pb1 = __shfl_sync(0xffffffffu, p10, j + 1);
                o0a += pa0 * va; o0b += pb0 * vc2;
                o1a += pa1 * va; o1b += pb1 * vc2;
            }
            #pragma unroll
            for (int j = 0; j < 16; j += 2) {
                float va = vb[(32 + j) * DIMC], vc2 = vb[(33 + j) * DIMC];
                float pa0 = __shfl_sync(0xffffffffu, p01, j);
                float pb0 = __shfl_sync(0xffffffffu, p01, j + 1);
                float pa1 = __shfl_sync(0xffffffffu, p11, j);
                float pb1 = __shfl_sync(0xffffffffu, p11, j + 1);
                o0a += pa0 * va; o0b += pb0 * vc2;
                o1a += pa1 * va; o1b += pb1 * vc2;
            }
            {   // j = 48
                float va = vb[48 * DIMC];
                float pa0 = __shfl_sync(0xffffffffu, p01, 16);
                float pa1 = __shfl_sync(0xffffffffu, p11, 16);
                o0a += pa0 * va;
                o1a += pa1 * va;
            }
            // write attention output over the q rows we just consumed
            sq[i0 * DIMC + h * HD + lane] = o0a + o0b;
            if (two) sq[i1 * DIMC + h * HD + lane] = o1a + o1b;
        }
    }
    __syncthreads();

    // ---- proj GEMM: [49,128] @ [128,128] + b  (packed f32x2) ----
    u64 pacc2[7][2];
    {
        ulonglong2 pb = *(const ulonglong2*)(proj_b + 4 * tx);
        #pragma unroll
        for (int i = 0; i < 7; ++i) { pacc2[i][0] = pb.x; pacc2[i][1] = pb.y; }
    }

    for (int c = 0; c < 8; ++c) {
        if (c < 7) cp_wait1(); else cp_wait0();
        __syncthreads();
        const float* wb = swb + (c & 1) * 2048;
        const int kc = c * 16;
        #pragma unroll
        for (int k2 = 0; k2 < 16; k2 += 2) {
            float2 xv2[7];
            #pragma unroll
            for (int i = 0; i < 7; ++i) {
                int r = ty + 8 * i; r = (r < WIN_N) ? r : (WIN_N - 1);
                xv2[i] = *(const float2*)(sq + r * DIMC + kc + k2);
            }
            #pragma unroll
            for (int s = 0; s < 2; ++s) {
                const int k = k2 + s;
                ulonglong2 wv = *(const ulonglong2*)(wb + k * DIMC + 4 * tx);
                #pragma unroll
                for (int i = 0; i < 7; ++i) {
                    u64 xp = dup2(s ? xv2[i].y : xv2[i].x);
                    ffma2(pacc2[i][0], xp, wv.x);
                    ffma2(pacc2[i][1], xp, wv.y);
                }
            }
        }
        __syncthreads();
        if (c + 2 < 8) {
            const float* src = proj_w + (c + 2) * 2048 + tid * 4;
            unsigned dst = swb_sa + ((c & 1) * 2048 + tid * 4) * 4;
            cp16(dst, src); cp16(dst + 4096, src + 1024);
            cp_commit();
        }
    }

    // ---- store ----
    {
        float* go = out + (size_t)b * (WIN_N * DIMC);
        #pragma unroll
        for (int i = 0; i < 7; ++i) {
            int r = ty + 8 * i;
            if (r < WIN_N) {
                float2 a = unpk(pacc2[i][0]), c2 = unpk(pacc2[i][1]);
                *(float4*)(go + r * DIMC + 4 * tx) = make_float4(a.x, a.y, c2.x, c2.y);
            }
        }
    }
}

extern "C" void kernel_launch(void* const* d_in, const int* in_sizes, int n_in,
                              void* d_out, int out_size)
{
    const float* x      = (const float*)d_in[0];
    const float* mask   = (const float*)d_in[1];
    const float* qkv_w  = (const float*)d_in[2];
    const float* qkv_b  = (const float*)d_in[3];
    const float* proj_w = (const float*)d_in[4];
    const float* proj_b = (const float*)d_in[5];
    const float* table  = (const float*)d_in[6];
    const int*   relidx = (const int*)d_in[7];
    float*       out    = (float*)d_out;

    const int B  = in_sizes[0] / (WIN_N * DIMC);
    const int nW = in_sizes[1] / (WIN_N * WIN_N);

    cudaFuncSetAttribute(win_attn_kernel,
                         cudaFuncAttributeMaxDynamicSharedMemorySize, SMEM_BYTES);
    win_attn_kernel<<<B, 256, SMEM_BYTES>>>(x, mask, qkv_w, qkv_b,
                                            proj_w, proj_b, table, relidx,
                                            out, nW);
}

// round 6
// speedup vs baseline: 1.6682x; 1.2058x over previous
#include <cuda_runtime.h>
#include <cuda_bf16.h>
#include <cstdint>

typedef unsigned int u32;

#define QSCALE 0.17677669529663687f

// fp32 smem array strides (floats)
#define QS    132          /* sq/sv row stride  */
#define SQW   6468         /* 49*132 per-window */
#define KTS   56
#define KTW   7168         /* 4*32*56 */

// ---- smem byte offsets ----
#define OFF_SQ   0          /* 2*6468*4 = 51744 */
#define OFF_KT   51744      /* 2*7168*4 = 57344 -> 109088 */
#define OFF_SV   109088     /* 51744 -> 160832 */
#define OFF_WB   161792     /* 2 x 16384 -> 194560 */
#define OFF_AHI  194560     /* k-half A hi 16384 */
#define OFF_ALO  210944     /* k-half A lo 16384 -> 227328 */
#define OFF_PHI  51744      /* proj A' hi (over dead kT) 32768 */
#define OFF_PLO  84512      /* proj A' lo (kT tail + sv head) 32768 */
#define SMEM_BYTES 227328

// pre-packed bf16 weight fragments: piece = 16KB = [ntile16][kstep4][lane32][8B]
// g_wq pieces: chunk(3) x khalf(2) x part(hi/lo)(2); g_wp: khalf(2) x part(2)
__device__ __align__(16) unsigned char g_wq[196608];
__device__ __align__(16) unsigned char g_wp[65536];

// ---------------- prep kernel: fp32 W -> bf16 hi/lo fragment pieces ----------------
__global__ void prep_weights(const float* __restrict__ qkv_w,
                             const float* __restrict__ proj_w) {
    int e = blockIdx.x * 256 + threadIdx.x;   // 32768 total
    bool isq = e < 24576;
    int idx = isq ? e : e - 24576;
    const float* W = isq ? qkv_w : proj_w;
    unsigned char* dst = isq ? g_wq : g_wp;
    int ldw = isq ? 384 : 128;
    int piece = idx >> 11;
    int rem   = idx & 2047;
    int lane  = rem & 31;
    int ks    = (rem >> 5) & 3;
    int nt    = rem >> 7;
    int chunk = isq ? (piece >> 2) : 0;
    int kh    = isq ? ((piece >> 1) & 1) : (piece >> 1);
    int part  = piece & 1;
    int k0 = kh * 64 + ks * 16 + (lane & 3) * 2;
    int n  = chunk * 128 + nt * 8 + (lane >> 2);
    float v0 = W[k0 * ldw + n],       v1 = W[(k0 + 1) * ldw + n];
    float v2 = W[(k0 + 8) * ldw + n], v3 = W[(k0 + 9) * ldw + n];
    __nv_bfloat16 h0 = __float2bfloat16_rn(v0), h1 = __float2bfloat16_rn(v1);
    __nv_bfloat16 h2 = __float2bfloat16_rn(v2), h3 = __float2bfloat16_rn(v3);
    __nv_bfloat162 r0, r1;
    if (part == 0) {
        r0 = __halves2bfloat162(h0, h1);
        r1 = __halves2bfloat162(h2, h3);
    } else {
        r0 = __halves2bfloat162(__float2bfloat16_rn(v0 - __bfloat162float(h0)),
                                __float2bfloat16_rn(v1 - __bfloat162float(h1)));
        r1 = __halves2bfloat162(__float2bfloat16_rn(v2 - __bfloat162float(h2)),
                                __float2bfloat16_rn(v3 - __bfloat162float(h3)));
    }
    *(__nv_bfloat162*)(dst + (size_t)idx * 8)     = r0;
    *(__nv_bfloat162*)(dst + (size_t)idx * 8 + 4) = r1;
}

// ---------------- PTX helpers (baseline PTX only) ----------------
__device__ __forceinline__ void cp16(u32 dst, const void* src) {
    asm volatile("cp.async.cg.shared.global [%0], [%1], 16;" :: "r"(dst), "l"(src));
}
__device__ __forceinline__ void cp_commit() { asm volatile("cp.async.commit_group;"); }
template <int N> __device__ __forceinline__ void cp_wait() {
    asm volatile("cp.async.wait_group %0;" :: "n"(N));
}
__device__ __forceinline__ void ldm4(u32 r[4], u32 addr) {
    asm volatile("ldmatrix.sync.aligned.m8n8.x4.shared.b16 {%0,%1,%2,%3}, [%4];"
        : "=r"(r[0]), "=r"(r[1]), "=r"(r[2]), "=r"(r[3]) : "r"(addr));
}
__device__ __forceinline__ void mma16816(float c[4], const u32 a[4], u32 b0, u32 b1) {
    asm volatile("mma.sync.aligned.m16n8k16.row.col.f32.bf16.bf16.f32 "
        "{%0,%1,%2,%3}, {%4,%5,%6,%7}, {%8,%9}, {%0,%1,%2,%3};"
        : "+f"(c[0]), "+f"(c[1]), "+f"(c[2]), "+f"(c[3])
        : "r"(a[0]), "r"(a[1]), "r"(a[2]), "r"(a[3]), "r"(b0), "r"(b1));
}

// issue one 16KB weight piece into ping-pong buffer (piece i -> buf i&1)
__device__ __forceinline__ void issue_piece(u32 sb, int i, int tid) {
    const unsigned char* src =
        (i < 12 ? g_wq + (u32)i * 16384 : g_wp + (u32)(i - 12) * 16384) + tid * 32;
    u32 dst = sb + OFF_WB + (u32)(i & 1) * 16384 + (u32)tid * 32;
    cp16(dst, src); cp16(dst + 16, src + 16);
    cp_commit();
}

// one k-half (4 ksteps) of mma over 2 m-tiles x 4 n-tiles
__device__ __forceinline__ void mma_tiles(float acc[2][4][4],
    u32 ahiB, u32 aloB, u32 bufB, int mg, int ng, int lane,
    int rowShift, int chBase, bool both)
{
    #pragma unroll
    for (int ks = 0; ks < 4; ++ks) {
        u32 a_hi[2][4], a_lo[2][4];
        #pragma unroll
        for (int mt = 0; mt < 2; ++mt) {
            int row = mg * 32 + mt * 16 + (lane & 7) + ((lane >> 3) & 1) * 8;
            u32 ch = (u32)(chBase + ks * 2 + (lane >> 4));
            u32 sw = ((ch ^ (u32)(row & 7)) << 4);
            ldm4(a_hi[mt], ahiB + ((u32)row << rowShift) + sw);
            if (both) ldm4(a_lo[mt], aloB + ((u32)row << rowShift) + sw);
        }
        u32 b0[4], b1[4];
        #pragma unroll
        for (int nt = 0; nt < 4; ++nt) {
            u32 addr = bufB + (u32)((((ng * 4 + nt) * 4 + ks) * 32 + lane) * 8);
            asm volatile("ld.shared.v2.b32 {%0,%1}, [%2];"
                : "=r"(b0[nt]), "=r"(b1[nt]) : "r"(addr));
        }
        #pragma unroll
        for (int mt = 0; mt < 2; ++mt)
            #pragma unroll
            for (int nt = 0; nt < 4; ++nt) {
                mma16816(acc[mt][nt], a_hi[mt], b0[nt], b1[nt]);
                if (both) mma16816(acc[mt][nt], a_lo[mt], b0[nt], b1[nt]);
            }
    }
}

// ---------------- main kernel: 2 windows per CTA ----------------
__global__ __launch_bounds__(512, 1)
void win_attn_hmma(const float* __restrict__ x,
                   const float* __restrict__ mask,
                   const float* __restrict__ qkv_b,
                   const float* __restrict__ proj_b,
                   const float* __restrict__ bias_table,
                   const int*   __restrict__ rel_index,
                   float* __restrict__ out, int nW)
{
    extern __shared__ __align__(1024) unsigned char sm[];
    const u32 sb = (u32)__cvta_generic_to_shared(sm);
    const int tid = threadIdx.x, lane = tid & 31, wid = tid >> 5;
    const int b = blockIdx.x;
    const int mg = wid >> 2, ng = wid & 3;

    // prologue: pieces 0,1 in flight
    issue_piece(sb, 0, tid);
    issue_piece(sb, 1, tid);

    const float* xw = x + (size_t)(2 * b) * 49 * 128;

    float* Qf  = (float*)(sm + OFF_SQ);
    float* KTf = (float*)(sm + OFF_KT);
    float* Vf  = (float*)(sm + OFF_SV);

    // ======== QKV: 3 chunks (q,k,v), k-halves, 3-pass bf16 ========
    #pragma unroll 1
    for (int c = 0; c < 3; ++c) {
        float acc[2][4][4];
        #pragma unroll
        for (int mt = 0; mt < 2; ++mt)
            #pragma unroll
            for (int nt = 0; nt < 4; ++nt)
                #pragma unroll
                for (int e = 0; e < 4; ++e) acc[mt][nt][e] = 0.f;

        #pragma unroll 1
        for (int kh = 0; kh < 2; ++kh) {
            // build A(kh) hi/lo from gmem x
            {
                int row = tid >> 2, cg = tid & 3;
                int win = row >> 6, nr = row & 63;
                float xv[16];
                if (nr < 49) {
                    const float4* src = (const float4*)(xw + ((size_t)win * 49 + nr) * 128
                                                        + kh * 64 + cg * 16);
                    #pragma unroll
                    for (int q = 0; q < 4; ++q) {
                        float4 t = src[q];
                        xv[4*q] = t.x; xv[4*q+1] = t.y; xv[4*q+2] = t.z; xv[4*q+3] = t.w;
                    }
                } else {
                    #pragma unroll
                    for (int q = 0; q < 16; ++q) xv[q] = 0.f;
                }
                #pragma unroll
                for (int h = 0; h < 2; ++h) {
                    u32 hi[4], lo[4];
                    #pragma unroll
                    for (int p = 0; p < 4; ++p) {
                        float a = xv[h*8 + 2*p], bb = xv[h*8 + 2*p + 1];
                        __nv_bfloat16 ha = __float2bfloat16_rn(a), hb = __float2bfloat16_rn(bb);
                        __nv_bfloat162 th = __halves2bfloat162(ha, hb);
                        __nv_bfloat162 tl = __halves2bfloat162(
                            __float2bfloat16_rn(a - __bfloat162float(ha)),
                            __float2bfloat16_rn(bb - __bfloat162float(hb)));
                        hi[p] = *(u32*)&th; lo[p] = *(u32*)&tl;
                    }
                    int ch = cg * 2 + h;
                    u32 a = (u32)row * 128 + (u32)((ch ^ (row & 7)) << 4);
                    *(uint4*)(sm + OFF_AHI + a) = make_uint4(hi[0], hi[1], hi[2], hi[3]);
                    *(uint4*)(sm + OFF_ALO + a) = make_uint4(lo[0], lo[1], lo[2], lo[3]);
                }
            }
            int p = c * 4 + kh * 2;
            // hi piece: A-hi*W-hi + A-lo*W-hi
            cp_wait<1>(); __syncthreads();
            mma_tiles(acc, sb + OFF_AHI, sb + OFF_ALO, sb + OFF_WB + (u32)(p & 1) * 16384,
                      mg, ng, lane, 7, 0, true);
            __syncthreads();
            issue_piece(sb, p + 2, tid);
            // lo piece: A-hi*W-lo
            cp_wait<1>(); __syncthreads();
            mma_tiles(acc, sb + OFF_AHI, sb + OFF_ALO, sb + OFF_WB + (u32)((p + 1) & 1) * 16384,
                      mg, ng, lane, 7, 0, false);
            __syncthreads();
            issue_piece(sb, p + 3, tid);
        }

        // chunk epilogue -> sq / kT / sv (+bias)
        {
            int rb = mg * 32 + (lane >> 2);
            int cb = ng * 32 + (lane & 3) * 2;
            #pragma unroll
            for (int mt = 0; mt < 2; ++mt)
                #pragma unroll
                for (int rh = 0; rh < 2; ++rh) {
                    int r = rb + mt * 16 + rh * 8;
                    int win = r >> 6, nr = r & 63;
                    if (nr < 49) {
                        #pragma unroll
                        for (int nt = 0; nt < 4; ++nt) {
                            int cc = cb + nt * 8;
                            float v0 = acc[mt][nt][rh*2]   + __ldg(qkv_b + c*128 + cc);
                            float v1 = acc[mt][nt][rh*2+1] + __ldg(qkv_b + c*128 + cc + 1);
                            if (c == 0) {
                                *(float2*)(Qf + win*SQW + nr*QS + cc) =
                                    make_float2(v0 * QSCALE, v1 * QSCALE);
                            } else if (c == 1) {
                                KTf[win*KTW + (cc>>5)*1792 + (cc&31)*KTS + nr] = v0;
                                KTf[win*KTW + ((cc+1)>>5)*1792 + ((cc+1)&31)*KTS + nr] = v1;
                            } else {
                                *(float2*)(Vf + win*SQW + nr*QS + cc) = make_float2(v0, v1);
                            }
                        }
                    }
                }
        }
    }
    __syncthreads();

    // ======== attention (fp32, proven round-2 scheme) ========
    {
        const int win = wid >> 3, h = (wid >> 1) & 3, sub = wid & 1;
        const float* masks = mask + (size_t)((2*b + win) % nW) * 2401;
        const float* kt = KTf + win * KTW + h * 1792;
        const float* vb = Vf + win * SQW + h * 32 + lane;
        float* qw = Qf + win * SQW;
        const int j1 = lane + 32;
        const bool vj1 = (j1 < 49);
        const int j1c = vj1 ? j1 : 0;

        for (int t = 0; t < 13; ++t) {
            int i0 = 4 * t + 2 * sub;
            if (i0 >= 49) break;
            int i1 = i0 + 1;
            bool two = (i1 < 49);
            int r1 = two ? i1 : i0;

            int   idx00 = rel_index[i0 * 49 + lane];
            int   idx01 = rel_index[i0 * 49 + j1c];
            int   idx10 = rel_index[r1 * 49 + lane];
            int   idx11 = rel_index[r1 * 49 + j1c];
            float m00 = masks[i0 * 49 + lane], m01 = masks[i0 * 49 + j1c];
            float m10 = masks[r1 * 49 + lane], m11 = masks[r1 * 49 + j1c];

            const float* q0 = qw + i0 * QS + h * 32;
            const float* q1 = qw + r1 * QS + h * 32;
            float a00 = 0.f, a01 = 0.f, a10 = 0.f, a11 = 0.f;
            #pragma unroll
            for (int d = 0; d < 32; ++d) {
                float k0 = kt[d * KTS + lane];
                float k1 = kt[d * KTS + j1c];
                float qa = q0[d], qb = q1[d];
                a00 += qa * k0; a01 += qa * k1;
                a10 += qb * k0; a11 += qb * k1;
            }
            a00 += bias_table[idx00 * 4 + h] + m00;
            a01 = vj1 ? (a01 + bias_table[idx01 * 4 + h] + m01) : -1e30f;
            a10 += bias_table[idx10 * 4 + h] + m10;
            a11 = vj1 ? (a11 + bias_table[idx11 * 4 + h] + m11) : -1e30f;

            float mx0 = fmaxf(a00, a01), mx1 = fmaxf(a10, a11);
            #pragma unroll
            for (int o = 16; o > 0; o >>= 1) {
                mx0 = fmaxf(mx0, __shfl_xor_sync(0xffffffffu, mx0, o));
                mx1 = fmaxf(mx1, __shfl_xor_sync(0xffffffffu, mx1, o));
            }
            float e00 = __expf(a00 - mx0), e01 = vj1 ? __expf(a01 - mx0) : 0.f;
            float e10 = __expf(a10 - mx1), e11 = vj1 ? __expf(a11 - mx1) : 0.f;
            float s0 = e00 + e01, s1 = e10 + e11;
            #pragma unroll
            for (int o = 16; o > 0; o >>= 1) {
                s0 += __shfl_xor_sync(0xffffffffu, s0, o);
                s1 += __shfl_xor_sync(0xffffffffu, s1, o);
            }
            float p00 = e00 / s0, p01 = e01 / s0;
            float p10 = e10 / s1, p11 = e11 / s1;

            float o0a = 0.f, o0b = 0.f, o1a = 0.f, o1b = 0.f;
            #pragma unroll
            for (int j = 0; j < 32; j += 2) {
                float va = vb[j * QS], vc2 = vb[(j + 1) * QS];
                float pa0 = __shfl_sync(0xffffffffu, p00, j);
                float pb0 = __shfl_sync(0xffffffffu, p00, j + 1);
                float pa1 = __shfl_sync(0xffffffffu, p10, j);
                float pb1 = __shfl_sync(0xffffffffu, p10, j + 1);
                o0a += pa0 * va; o0b += pb0 * vc2;
                o1a += pa1 * va; o1b += pb1 * vc2;
            }
            #pragma unroll
            for (int j = 0; j < 16; j += 2) {
                float va = vb[(32 + j) * QS], vc2 = vb[(33 + j) * QS];
                float pa0 = __shfl_sync(0xffffffffu, p01, j);
                float pb0 = __shfl_sync(0xffffffffu, p01, j + 1);
                float pa1 = __shfl_sync(0xffffffffu, p11, j);
                float pb1 = __shfl_sync(0xffffffffu, p11, j + 1);
                o0a += pa0 * va; o0b += pb0 * vc2;
                o1a += pa1 * va; o1b += pb1 * vc2;
            }
            {
                float va = vb[48 * QS];
                float pa0 = __shfl_sync(0xffffffffu, p01, 16);
                float pa1 = __shfl_sync(0xffffffffu, p11, 16);
                o0a += pa0 * va;
                o1a += pa1 * va;
            }
            qw[i0 * QS + h * 32 + lane] = o0a + o0b;
            if (two) qw[i1 * QS + h * 32 + lane] = o1a + o1b;
        }
    }
    __syncthreads();

    // ======== build proj A' hi/lo (full 128-K rows) from sq ========
    {
        int row = tid >> 2, cg = tid & 3;
        int win = row >> 6, nr = row & 63;
        float xv[32];
        if (nr < 49) {
            const float4* src = (const float4*)(Qf + win*SQW + nr*QS + cg*32);
            #pragma unroll
            for (int q = 0; q < 8; ++q) {
                float4 t = src[q];
                xv[4*q] = t.x; xv[4*q+1] = t.y; xv[4*q+2] = t.z; xv[4*q+3] = t.w;
            }
        } else {
            #pragma unroll
            for (int q = 0; q < 32; ++q) xv[q] = 0.f;
        }
        #pragma unroll
        for (int h = 0; h < 4; ++h) {
            u32 hi[4], lo[4];
            #pragma unroll
            for (int p = 0; p < 4; ++p) {
                float a = xv[h*8 + 2*p], bb = xv[h*8 + 2*p + 1];
                __nv_bfloat16 ha = __float2bfloat16_rn(a), hb = __float2bfloat16_rn(bb);
                __nv_bfloat162 th = __halves2bfloat162(ha, hb);
                __nv_bfloat162 tl = __halves2bfloat162(
                    __float2bfloat16_rn(a - __bfloat162float(ha)),
                    __float2bfloat16_rn(bb - __bfloat162float(hb)));
                hi[p] = *(u32*)&th; lo[p] = *(u32*)&tl;
            }
            int ch = cg * 4 + h;
            u32 a = (u32)row * 256 + (u32)((ch ^ (row & 7)) << 4);
            *(uint4*)(sm + OFF_PHI + a) = make_uint4(hi[0], hi[1], hi[2], hi[3]);
            *(uint4*)(sm + OFF_PLO + a) = make_uint4(lo[0], lo[1], lo[2], lo[3]);
        }
    }
    __syncthreads();

    // ======== proj GEMM (pieces 12..15) ========
    float pacc[2][4][4];
    #pragma unroll
    for (int mt = 0; mt < 2; ++mt)
        #pragma unroll
        for (int nt = 0; nt < 4; ++nt)
            #pragma unroll
            for (int e = 0; e < 4; ++e) pacc[mt][nt][e] = 0.f;

    // kh = 0: pieces 12 (hi, buf0), 13 (lo, buf1)
    cp_wait<1>(); __syncthreads();
    mma_tiles(pacc, sb + OFF_PHI, sb + OFF_PLO, sb + OFF_WB, mg, ng, lane, 8, 0, true);
    __syncthreads();
    issue_piece(sb, 14, tid);
    cp_wait<1>(); __syncthreads();
    mma_tiles(pacc, sb + OFF_PHI, sb + OFF_PLO, sb + OFF_WB + 16384, mg, ng, lane, 8, 0, false);
    __syncthreads();
    issue_piece(sb, 15, tid);
    // kh = 1: pieces 14 (hi, buf0), 15 (lo, buf1)
    cp_wait<1>(); __syncthreads();
    mma_tiles(pacc, sb + OFF_PHI, sb + OFF_PLO, sb + OFF_WB, mg, ng, lane, 8, 8, true);
    __syncthreads();
    cp_wait<0>(); __syncthreads();
    mma_tiles(pacc, sb + OFF_PHI, sb + OFF_PLO, sb + OFF_WB + 16384, mg, ng, lane, 8, 8, false);

    // proj epilogue -> gmem (+bias)
    {
        int rb = mg * 32 + (lane >> 2);
        int cb = ng * 32 + (lane & 3) * 2;
        #pragma unroll
        for (int mt = 0; mt < 2; ++mt)
            #pragma unroll
            for (int rh = 0; rh < 2; ++rh) {
                int r = rb + mt * 16 + rh * 8;
                int win = r >> 6, nr = r & 63;
                if (nr < 49) {
                    float* go = out + ((size_t)(2*b + win) * 49 + nr) * 128;
                    #pragma unroll
                    for (int nt = 0; nt < 4; ++nt) {
                        int cc = cb + nt * 8;
                        float v0 = pacc[mt][nt][rh*2]   + __ldg(proj_b + cc);
                        float v1 = pacc[mt][nt][rh*2+1] + __ldg(proj_b + cc + 1);
                        *(float2*)(go + cc) = make_float2(v0, v1);
                    }
                }
            }
    }
}

extern "C" void kernel_launch(void* const* d_in, const int* in_sizes, int n_in,
                              void* d_out, int out_size)
{
    const float* x      = (const float*)d_in[0];
    const float* mask   = (const float*)d_in[1];
    const float* qkv_w  = (const float*)d_in[2];
    const float* qkv_b  = (const float*)d_in[3];
    const float* proj_w = (const float*)d_in[4];
    const float* proj_b = (const float*)d_in[5];
    const float* table  = (const float*)d_in[6];
    const int*   relidx = (const int*)d_in[7];
    float*       out    = (float*)d_out;

    const int B  = in_sizes[0] / (49 * 128);
    const int nW = in_sizes[1] / (49 * 49);

    prep_weights<<<128, 256>>>(qkv_w, proj_w);

    cudaFuncSetAttribute(win_attn_hmma,
                         cudaFuncAttributeMaxDynamicSharedMemorySize, SMEM_BYTES);
    win_attn_hmma<<<B / 2, 512, SMEM_BYTES>>>(x, mask, qkv_b, proj_b,
                                              table, relidx, out, nW);
}

// round 7
// speedup vs baseline: 3.1232x; 1.8722x over previous
#include <cuda_runtime.h>
#include <cuda_bf16.h>
#include <cstdint>

typedef unsigned int u32;

#define QSCALE 0.17677669529663687f

// ---- smem byte offsets ----
#define OFF_WB    0         /* 2 x 16384 weight ping-pong            */
#define OFF_QHI   32768     /* Q bf16 hi  [128 rows][256B]           */
#define OFF_QLO   65536
#define OFF_KHI   98304     /* K bf16 hi  [112 rows (2x56)][256B]    */
#define OFF_KLO   126976
#define OFF_VTHI  155648    /* VT bf16 hi [256 rows (2x128)][128B]   */
#define OFF_VTLO  188416
#define OFF_AHI   155648    /* QKV-GEMM A staging (aliases VTHI)     */
#define OFF_ALO   172032
#define OFF_PHI   32768     /* proj A' hi (aliases Q hi)             */
#define OFF_PLO   65536     /* proj A' lo (aliases Q lo)             */
#define SMEM_BYTES 221184

// pre-packed bf16 weight fragments (as round 6 — validated)
__device__ __align__(16) unsigned char g_wq[196608];
__device__ __align__(16) unsigned char g_wp[65536];
// combined bias+mask table: [w<64][h<4][i<49][j stride 56]
__device__ __align__(16) float g_bm[702464];

__device__ __forceinline__ u32 sw16(int ch, int r) {
    return (u32)((ch & 8) | ((ch ^ (r & 7)) & 7));
}

// ---------------- prep kernel: weights + bias/mask table ----------------
__global__ void prep_all(const float* __restrict__ qkv_w,
                         const float* __restrict__ proj_w,
                         const float* __restrict__ mask,
                         const float* __restrict__ bias_table,
                         const int*   __restrict__ rel_index,
                         int nW) {
    int e = blockIdx.x * 256 + threadIdx.x;
    if (e < 32768) {
        bool isq = e < 24576;
        int idx = isq ? e : e - 24576;
        const float* W = isq ? qkv_w : proj_w;
        unsigned char* dst = isq ? g_wq : g_wp;
        int ldw = isq ? 384 : 128;
        int piece = idx >> 11;
        int rem = idx & 2047;
        int lane = rem & 31, ks = (rem >> 5) & 3, nt = rem >> 7;
        int chunk = isq ? (piece >> 2) : 0;
        int kh = isq ? ((piece >> 1) & 1) : (piece >> 1);
        int part = piece & 1;
        int k0 = kh * 64 + ks * 16 + (lane & 3) * 2;
        int n  = chunk * 128 + nt * 8 + (lane >> 2);
        float v0 = W[k0 * ldw + n],       v1 = W[(k0 + 1) * ldw + n];
        float v2 = W[(k0 + 8) * ldw + n], v3 = W[(k0 + 9) * ldw + n];
        __nv_bfloat16 h0 = __float2bfloat16_rn(v0), h1 = __float2bfloat16_rn(v1);
        __nv_bfloat16 h2 = __float2bfloat16_rn(v2), h3 = __float2bfloat16_rn(v3);
        __nv_bfloat162 r0, r1;
        if (part == 0) {
            r0 = __halves2bfloat162(h0, h1);
            r1 = __halves2bfloat162(h2, h3);
        } else {
            r0 = __halves2bfloat162(__float2bfloat16_rn(v0 - __bfloat162float(h0)),
                                    __float2bfloat16_rn(v1 - __bfloat162float(h1)));
            r1 = __halves2bfloat162(__float2bfloat16_rn(v2 - __bfloat162float(h2)),
                                    __float2bfloat16_rn(v3 - __bfloat162float(h3)));
        }
        *(__nv_bfloat162*)(dst + (size_t)idx * 8)     = r0;
        *(__nv_bfloat162*)(dst + (size_t)idx * 8 + 4) = r1;
    } else {
        int idx = e - 32768;                  // < 702464
        if (idx < 702464) {
            int w = idx / 10976;
            int r = idx % 10976;
            int h = r / 2744;
            int r2 = r % 2744;
            int i = r2 / 56, j = r2 % 56;
            float val = 0.f;
            if (j < 49 && w < nW)
                val = bias_table[rel_index[i * 49 + j] * 4 + h] + mask[w * 2401 + i * 49 + j];
            g_bm[idx] = val;
        }
    }
}

// ---------------- PTX helpers ----------------
__device__ __forceinline__ void cp16(u32 dst, const void* src) {
    asm volatile("cp.async.cg.shared.global [%0], [%1], 16;" :: "r"(dst), "l"(src));
}
__device__ __forceinline__ void cp_commit() { asm volatile("cp.async.commit_group;"); }
template <int N> __device__ __forceinline__ void cp_wait() {
    asm volatile("cp.async.wait_group %0;" :: "n"(N));
}
__device__ __forceinline__ void ldm4(u32 r[4], u32 addr) {
    asm volatile("ldmatrix.sync.aligned.m8n8.x4.shared.b16 {%0,%1,%2,%3}, [%4];"
        : "=r"(r[0]), "=r"(r[1]), "=r"(r[2]), "=r"(r[3]) : "r"(addr));
}
__device__ __forceinline__ void ldm2(u32 r[2], u32 addr) {
    asm volatile("ldmatrix.sync.aligned.m8n8.x2.shared.b16 {%0,%1}, [%2];"
        : "=r"(r[0]), "=r"(r[1]) : "r"(addr));
}
__device__ __forceinline__ void mma16816(float c[4], const u32 a[4], u32 b0, u32 b1) {
    asm volatile("mma.sync.aligned.m16n8k16.row.col.f32.bf16.bf16.f32 "
        "{%0,%1,%2,%3}, {%4,%5,%6,%7}, {%8,%9}, {%0,%1,%2,%3};"
        : "+f"(c[0]), "+f"(c[1]), "+f"(c[2]), "+f"(c[3])
        : "r"(a[0]), "r"(a[1]), "r"(a[2]), "r"(a[3]), "r"(b0), "r"(b1));
}
__device__ __forceinline__ u32 pk_hi(float a, float b) {
    __nv_bfloat162 t = __halves2bfloat162(__float2bfloat16_rn(a), __float2bfloat16_rn(b));
    return *(u32*)&t;
}
__device__ __forceinline__ u32 pk_lo(float a, float b) {
    __nv_bfloat16 ha = __float2bfloat16_rn(a), hb = __float2bfloat16_rn(b);
    __nv_bfloat162 t = __halves2bfloat162(
        __float2bfloat16_rn(a - __bfloat162float(ha)),
        __float2bfloat16_rn(b - __bfloat162float(hb)));
    return *(u32*)&t;
}

// issue one 16KB weight piece into ping-pong buffer (piece i -> buf i&1)
__device__ __forceinline__ void issue_piece(u32 sb, int i, int tid) {
    const unsigned char* src =
        (i < 12 ? g_wq + (u32)i * 16384 : g_wp + (u32)(i - 12) * 16384) + tid * 32;
    u32 dst = sb + OFF_WB + (u32)(i & 1) * 16384 + (u32)tid * 32;
    cp16(dst, src); cp16(dst + 16, src + 16);
    cp_commit();
}

// one k-half (4 ksteps) of mma over 2 m-tiles x 4 n-tiles (weight GEMMs)
__device__ __forceinline__ void mma_tiles(float acc[2][4][4],
    u32 ahiB, u32 aloB, u32 bufB, int mg, int ng, int lane,
    int rowShift, int chBase, bool both)
{
    #pragma unroll
    for (int ks = 0; ks < 4; ++ks) {
        u32 a_hi[2][4], a_lo[2][4];
        #pragma unroll
        for (int mt = 0; mt < 2; ++mt) {
            int row = mg * 32 + mt * 16 + (lane & 7) + ((lane >> 3) & 1) * 8;
            u32 ch = (u32)(chBase + ks * 2 + (lane >> 4));
            u32 sw = ((ch ^ (u32)(row & 7)) << 4);
            ldm4(a_hi[mt], ahiB + ((u32)row << rowShift) + sw);
            if (both) ldm4(a_lo[mt], aloB + ((u32)row << rowShift) + sw);
        }
        u32 b0[4], b1[4];
        #pragma unroll
        for (int nt = 0; nt < 4; ++nt) {
            u32 addr = bufB + (u32)((((ng * 4 + nt) * 4 + ks) * 32 + lane) * 8);
            asm volatile("ld.shared.v2.b32 {%0,%1}, [%2];"
                : "=r"(b0[nt]), "=r"(b1[nt]) : "r"(addr));
        }
        #pragma unroll
        for (int mt = 0; mt < 2; ++mt)
            #pragma unroll
            for (int nt = 0; nt < 4; ++nt) {
                mma16816(acc[mt][nt], a_hi[mt], b0[nt], b1[nt]);
                if (both) mma16816(acc[mt][nt], a_lo[mt], b0[nt], b1[nt]);
            }
    }
}

// ---------------- main kernel: 2 windows per CTA, all-HMMA ----------------
__global__ __launch_bounds__(512, 1)
void win_attn_fa(const float* __restrict__ x,
                 const float* __restrict__ qkv_b,
                 const float* __restrict__ proj_b,
                 float* __restrict__ out, int nW)
{
    extern __shared__ __align__(1024) unsigned char sm[];
    const u32 sb = (u32)__cvta_generic_to_shared(sm);
    const int tid = threadIdx.x, lane = tid & 31, wid = tid >> 5;
    const int b = blockIdx.x;
    const int mg = wid >> 2, ng = wid & 3;

    issue_piece(sb, 0, tid);
    issue_piece(sb, 1, tid);

    const float* xw = x + (size_t)(2 * b) * 49 * 128;

    // ======== QKV GEMM: 3 chunks (q,k,v) ========
    #pragma unroll 1
    for (int c = 0; c < 3; ++c) {
        float acc[2][4][4];
        #pragma unroll
        for (int mt = 0; mt < 2; ++mt)
            #pragma unroll
            for (int nt = 0; nt < 4; ++nt)
                #pragma unroll
                for (int e = 0; e < 4; ++e) acc[mt][nt][e] = 0.f;

        #pragma unroll 1
        for (int kh = 0; kh < 2; ++kh) {
            // build A(kh) hi/lo from gmem x (staging aliases VT region)
            {
                int row = tid >> 2, cg = tid & 3;
                int win = row >> 6, nr = row & 63;
                float xv[16];
                if (nr < 49) {
                    const float4* src = (const float4*)(xw + ((size_t)win * 49 + nr) * 128
                                                        + kh * 64 + cg * 16);
                    #pragma unroll
                    for (int q = 0; q < 4; ++q) {
                        float4 t = src[q];
                        xv[4*q] = t.x; xv[4*q+1] = t.y; xv[4*q+2] = t.z; xv[4*q+3] = t.w;
                    }
                } else {
                    #pragma unroll
                    for (int q = 0; q < 16; ++q) xv[q] = 0.f;
                }
                #pragma unroll
                for (int h = 0; h < 2; ++h) {
                    u32 hi[4], lo[4];
                    #pragma unroll
                    for (int p = 0; p < 4; ++p) {
                        float a = xv[h*8 + 2*p], bb = xv[h*8 + 2*p + 1];
                        hi[p] = pk_hi(a, bb);
                        lo[p] = pk_lo(a, bb);
                    }
                    int ch = cg * 2 + h;
                    u32 a = (u32)row * 128 + (u32)((ch ^ (row & 7)) << 4);
                    *(uint4*)(sm + OFF_AHI + a) = make_uint4(hi[0], hi[1], hi[2], hi[3]);
                    *(uint4*)(sm + OFF_ALO + a) = make_uint4(lo[0], lo[1], lo[2], lo[3]);
                }
            }
            int p = c * 4 + kh * 2;
            cp_wait<1>(); __syncthreads();
            mma_tiles(acc, sb + OFF_AHI, sb + OFF_ALO, sb + OFF_WB + (u32)(p & 1) * 16384,
                      mg, ng, lane, 7, 0, true);
            __syncthreads();
            issue_piece(sb, p + 2, tid);
            cp_wait<1>(); __syncthreads();
            mma_tiles(acc, sb + OFF_AHI, sb + OFF_ALO, sb + OFF_WB + (u32)((p + 1) & 1) * 16384,
                      mg, ng, lane, 7, 0, false);
            __syncthreads();
            issue_piece(sb, p + 3, tid);
        }

        // epilogue: write Q / K / VT as bf16 hi/lo (pad rows/cols zeroed)
        {
            int rb = mg * 32 + (lane >> 2);
            int cb = ng * 32 + (lane & 3) * 2;
            #pragma unroll
            for (int mt = 0; mt < 2; ++mt)
                #pragma unroll
                for (int rh = 0; rh < 2; ++rh) {
                    int r = rb + mt * 16 + rh * 8;
                    int win = r >> 6, nr = r & 63;
                    bool ok = nr < 49;
                    #pragma unroll
                    for (int nt = 0; nt < 4; ++nt) {
                        int cc = cb + nt * 8;
                        float v0 = acc[mt][nt][rh*2]   + __ldg(qkv_b + c*128 + cc);
                        float v1 = acc[mt][nt][rh*2+1] + __ldg(qkv_b + c*128 + cc + 1);
                        if (c == 0) {
                            v0 = ok ? v0 * QSCALE : 0.f;
                            v1 = ok ? v1 * QSCALE : 0.f;
                            u32 byte = (u32)r * 256 + sw16(cc >> 3, r) * 16 + (cc & 7) * 2;
                            *(u32*)(sm + OFF_QHI + byte) = pk_hi(v0, v1);
                            *(u32*)(sm + OFF_QLO + byte) = pk_lo(v0, v1);
                        } else if (c == 1) {
                            if (nr < 56) {
                                v0 = ok ? v0 : 0.f; v1 = ok ? v1 : 0.f;
                                int kr = win * 56 + nr;
                                u32 byte = (u32)kr * 256 + sw16(cc >> 3, kr) * 16 + (cc & 7) * 2;
                                *(u32*)(sm + OFF_KHI + byte) = pk_hi(v0, v1);
                                *(u32*)(sm + OFF_KLO + byte) = pk_lo(v0, v1);
                            }
                        } else {
                            v0 = ok ? v0 : 0.f; v1 = ok ? v1 : 0.f;
                            #pragma unroll
                            for (int e = 0; e < 2; ++e) {
                                float vv = e ? v1 : v0;
                                int vr = win * 128 + cc + e;
                                u32 byte = (u32)vr * 128
                                         + (u32)((((nr >> 3) ^ (vr & 7)) & 7) << 4)
                                         + (nr & 7) * 2;
                                __nv_bfloat16 hb = __float2bfloat16_rn(vv);
                                *(__nv_bfloat16*)(sm + OFF_VTHI + byte) = hb;
                                *(__nv_bfloat16*)(sm + OFF_VTLO + byte) =
                                    __float2bfloat16_rn(vv - __bfloat162float(hb));
                            }
                        }
                    }
                }
        }
    }
    __syncthreads();   // Q/K/VT visible to all warps

    // ======== attention: unit = (win, head), warp handles 2 m-tiles ========
    {
        const int unit = wid >> 1, win = unit >> 2, h = unit & 3;
        const int g = lane >> 2, t = lane & 3;
        const float* bm = g_bm + ((size_t)((2 * b + win) % nW) * 4 + h) * 2744;

        #pragma unroll 1
        for (int tk = 0; tk < 2; ++tk) {
            const int mt = (wid & 1) * 2 + tk;

            // ---- S = Q @ K^T (3-pass hi/lo) ----
            float s[7][4];
            #pragma unroll
            for (int nt = 0; nt < 7; ++nt)
                #pragma unroll
                for (int e = 0; e < 4; ++e) s[nt][e] = 0.f;

            u32 aqh[2][4], aql[2][4];
            #pragma unroll
            for (int ks = 0; ks < 2; ++ks) {
                int rr = win * 64 + mt * 16 + (lane & 7) + ((lane >> 3) & 1) * 8;
                int ch = h * 4 + ks * 2 + (lane >> 4);
                u32 off = (u32)rr * 256 + sw16(ch, rr) * 16;
                ldm4(aqh[ks], sb + OFF_QHI + off);
                ldm4(aql[ks], sb + OFF_QLO + off);
            }
            #pragma unroll
            for (int ks = 0; ks < 2; ++ks) {
                u32 bkh[7][2], bkl[7][2];
                #pragma unroll
                for (int ntp = 0; ntp < 3; ++ntp) {
                    int kr = win * 56 + ntp * 16 + ((lane >> 4) << 3) + (lane & 7);
                    int ch = h * 4 + ks * 2 + ((lane >> 3) & 1);
                    u32 off = (u32)kr * 256 + sw16(ch, kr) * 16;
                    u32 r4[4];
                    ldm4(r4, sb + OFF_KHI + off);
                    bkh[2*ntp][0] = r4[0]; bkh[2*ntp][1] = r4[1];
                    bkh[2*ntp+1][0] = r4[2]; bkh[2*ntp+1][1] = r4[3];
                    ldm4(r4, sb + OFF_KLO + off);
                    bkl[2*ntp][0] = r4[0]; bkl[2*ntp][1] = r4[1];
                    bkl[2*ntp+1][0] = r4[2]; bkl[2*ntp+1][1] = r4[3];
                }
                {
                    int kr = win * 56 + 48 + (lane & 7);
                    int ch = h * 4 + ks * 2 + ((lane >> 3) & 1);
                    u32 off = (u32)kr * 256 + sw16(ch, kr) * 16;
                    ldm2(bkh[6], sb + OFF_KHI + off);
                    ldm2(bkl[6], sb + OFF_KLO + off);
                }
                #pragma unroll
                for (int nt = 0; nt < 7; ++nt) {
                    mma16816(s[nt], aqh[ks], bkh[nt][0], bkh[nt][1]);
                    mma16816(s[nt], aql[ks], bkh[nt][0], bkh[nt][1]);
                    mma16816(s[nt], aqh[ks], bkl[nt][0], bkl[nt][1]);
                }
            }

            // ---- +bias+mask, softmax (rows g, g+8; quad reductions) ----
            {
                int i0 = mt * 16 + g;
                int o0 = min(i0, 48) * 56, o1 = min(i0 + 8, 48) * 56;
                #pragma unroll
                for (int nt = 0; nt < 7; ++nt) {
                    int jj = nt * 8 + 2 * t;
                    float2 b0 = *(const float2*)(bm + o0 + jj);
                    float2 b1 = *(const float2*)(bm + o1 + jj);
                    s[nt][0] = (jj     < 49) ? s[nt][0] + b0.x : -1e30f;
                    s[nt][1] = (jj + 1 < 49) ? s[nt][1] + b0.y : -1e30f;
                    s[nt][2] = (jj     < 49) ? s[nt][2] + b1.x : -1e30f;
                    s[nt][3] = (jj + 1 < 49) ? s[nt][3] + b1.y : -1e30f;
                }
                float m0 = -1e30f, m1 = -1e30f;
                #pragma unroll
                for (int nt = 0; nt < 7; ++nt) {
                    m0 = fmaxf(m0, fmaxf(s[nt][0], s[nt][1]));
                    m1 = fmaxf(m1, fmaxf(s[nt][2], s[nt][3]));
                }
                m0 = fmaxf(m0, __shfl_xor_sync(0xffffffffu, m0, 1));
                m1 = fmaxf(m1, __shfl_xor_sync(0xffffffffu, m1, 1));
                m0 = fmaxf(m0, __shfl_xor_sync(0xffffffffu, m0, 2));
                m1 = fmaxf(m1, __shfl_xor_sync(0xffffffffu, m1, 2));
                float s0 = 0.f, s1 = 0.f;
                #pragma unroll
                for (int nt = 0; nt < 7; ++nt) {
                    s[nt][0] = __expf(s[nt][0] - m0); s0 += s[nt][0];
                    s[nt][1] = __expf(s[nt][1] - m0); s0 += s[nt][1];
                    s[nt][2] = __expf(s[nt][2] - m1); s1 += s[nt][2];
                    s[nt][3] = __expf(s[nt][3] - m1); s1 += s[nt][3];
                }
                s0 += __shfl_xor_sync(0xffffffffu, s0, 1);
                s1 += __shfl_xor_sync(0xffffffffu, s1, 1);
                s0 += __shfl_xor_sync(0xffffffffu, s0, 2);
                s1 += __shfl_xor_sync(0xffffffffu, s1, 2);
                float i0v = 1.f / s0, i1v = 1.f / s1;
                #pragma unroll
                for (int nt = 0; nt < 7; ++nt) {
                    s[nt][0] *= i0v; s[nt][1] *= i0v;
                    s[nt][2] *= i1v; s[nt][3] *= i1v;
                }
            }

            // ---- pack P fragments (S frags map 1:1 onto A frags) ----
            u32 ph[4][4], pl[4][4];
            #pragma unroll
            for (int k2 = 0; k2 < 4; ++k2) {
                int na = 2 * k2, nb = 2 * k2 + 1;
                ph[k2][0] = pk_hi(s[na][0], s[na][1]);
                ph[k2][1] = pk_hi(s[na][2], s[na][3]);
                pl[k2][0] = pk_lo(s[na][0], s[na][1]);
                pl[k2][1] = pk_lo(s[na][2], s[na][3]);
                if (nb < 7) {
                    ph[k2][2] = pk_hi(s[nb][0], s[nb][1]);
                    ph[k2][3] = pk_hi(s[nb][2], s[nb][3]);
                    pl[k2][2] = pk_lo(s[nb][0], s[nb][1]);
                    pl[k2][3] = pk_lo(s[nb][2], s[nb][3]);
                } else {
                    ph[k2][2] = ph[k2][3] = pl[k2][2] = pl[k2][3] = 0u;
                }
            }

            // ---- O = P @ V (3-pass) ----
            float o[4][4];
            #pragma unroll
            for (int nt = 0; nt < 4; ++nt)
                #pragma unroll
                for (int e = 0; e < 4; ++e) o[nt][e] = 0.f;
            #pragma unroll
            for (int k2 = 0; k2 < 4; ++k2) {
                u32 bvh[4][2], bvl[4][2];
                #pragma unroll
                for (int dp = 0; dp < 2; ++dp) {
                    int vr = win * 128 + h * 32 + dp * 16 + ((lane >> 4) << 3) + (lane & 7);
                    int ch = k2 * 2 + ((lane >> 3) & 1);
                    u32 off = (u32)vr * 128 + (u32)(((ch ^ (vr & 7)) & 7) << 4);
                    u32 r4[4];
                    ldm4(r4, sb + OFF_VTHI + off);
                    bvh[2*dp][0] = r4[0]; bvh[2*dp][1] = r4[1];
                    bvh[2*dp+1][0] = r4[2]; bvh[2*dp+1][1] = r4[3];
                    ldm4(r4, sb + OFF_VTLO + off);
                    bvl[2*dp][0] = r4[0]; bvl[2*dp][1] = r4[1];
                    bvl[2*dp+1][0] = r4[2]; bvl[2*dp+1][1] = r4[3];
                }
                #pragma unroll
                for (int nt = 0; nt < 4; ++nt) {
                    mma16816(o[nt], ph[k2], bvh[nt][0], bvh[nt][1]);
                    mma16816(o[nt], pl[k2], bvh[nt][0], bvh[nt][1]);
                    mma16816(o[nt], ph[k2], bvl[nt][0], bvl[nt][1]);
                }
            }

            // ---- write O hi/lo into proj-A layout (aliases dead Q chunks) ----
            #pragma unroll
            for (int nt = 0; nt < 4; ++nt)
                #pragma unroll
                for (int rh = 0; rh < 2; ++rh) {
                    int r = win * 64 + mt * 16 + g + rh * 8;
                    int col = h * 32 + nt * 8 + 2 * t;
                    u32 byte = (u32)r * 256 + sw16(col >> 3, r) * 16 + (col & 7) * 2;
                    *(u32*)(sm + OFF_PHI + byte) = pk_hi(o[nt][rh*2], o[nt][rh*2+1]);
                    *(u32*)(sm + OFF_PLO + byte) = pk_lo(o[nt][rh*2], o[nt][rh*2+1]);
                }
        }
    }
    __syncthreads();

    // ======== proj GEMM (pieces 12..15, issued during QKV tail) ========
    float pacc[2][4][4];
    #pragma unroll
    for (int mt = 0; mt < 2; ++mt)
        #pragma unroll
        for (int nt = 0; nt < 4; ++nt)
            #pragma unroll
            for (int e = 0; e < 4; ++e) pacc[mt][nt][e] = 0.f;

    cp_wait<1>(); __syncthreads();
    mma_tiles(pacc, sb + OFF_PHI, sb + OFF_PLO, sb + OFF_WB, mg, ng, lane, 8, 0, true);
    __syncthreads();
    issue_piece(sb, 14, tid);
    cp_wait<1>(); __syncthreads();
    mma_tiles(pacc, sb + OFF_PHI, sb + OFF_PLO, sb + OFF_WB + 16384, mg, ng, lane, 8, 0, false);
    __syncthreads();
    issue_piece(sb, 15, tid);
    cp_wait<1>(); __syncthreads();
    mma_tiles(pacc, sb + OFF_PHI, sb + OFF_PLO, sb + OFF_WB, mg, ng, lane, 8, 8, true);
    __syncthreads();
    cp_wait<0>(); __syncthreads();
    mma_tiles(pacc, sb + OFF_PHI, sb + OFF_PLO, sb + OFF_WB + 16384, mg, ng, lane, 8, 8, false);

    // proj epilogue -> gmem (+bias)
    {
        int rb = mg * 32 + (lane >> 2);
        int cb = ng * 32 + (lane & 3) * 2;
        #pragma unroll
        for (int mt = 0; mt < 2; ++mt)
            #pragma unroll
            for (int rh = 0; rh < 2; ++rh) {
                int r = rb + mt * 16 + rh * 8;
                int win = r >> 6, nr = r & 63;
                if (nr < 49) {
                    float* go = out + ((size_t)(2*b + win) * 49 + nr) * 128;
                    #pragma unroll
                    for (int nt = 0; nt < 4; ++nt) {
                        int cc = cb + nt * 8;
                        float v0 = pacc[mt][nt][rh*2]   + __ldg(proj_b + cc);
                        float v1 = pacc[mt][nt][rh*2+1] + __ldg(proj_b + cc + 1);
                        *(float2*)(go + cc) = make_float2(v0, v1);
                    }
                }
            }
    }
}

extern "C" void kernel_launch(void* const* d_in, const int* in_sizes, int n_in,
                              void* d_out, int out_size)
{
    const float* x      = (const float*)d_in[0];
    const float* mask   = (const float*)d_in[1];
    const float* qkv_w  = (const float*)d_in[2];
    const float* qkv_b  = (const float*)d_in[3];
    const float* proj_w = (const float*)d_in[4];
    const float* proj_b = (const float*)d_in[5];
    const float* table  = (const float*)d_in[6];
    const int*   relidx = (const int*)d_in[7];
    float*       out    = (float*)d_out;

    const int B  = in_sizes[0] / (49 * 128);
    const int nW = in_sizes[1] / (49 * 49);

    prep_all<<<2872, 256>>>(qkv_w, proj_w, mask, table, relidx, nW);

    cudaFuncSetAttribute(win_attn_fa,
                         cudaFuncAttributeMaxDynamicSharedMemorySize, SMEM_BYTES);
    win_attn_fa<<<B / 2, 512, SMEM_BYTES>>>(x, qkv_b, proj_b, out, nW);
}